// round 2
// baseline (speedup 1.0000x reference)
#include <cuda_runtime.h>
#include <math.h>

// ---------------------------------------------------------------------------
// MarkovBlanketAttention  (B=2, S=1024, DIN=512, DH=1024, H=16, HD=64)
// R1: batched multi-term fp32 GEMMs (occupancy fix), z-batched attention.
// ---------------------------------------------------------------------------

namespace {
constexpr int B_   = 2;
constexpr int S_   = 1024;
constexpr int DIN_ = 512;
constexpr int DH_  = 1024;
constexpr int H_   = 16;
constexpr int HD_  = 64;
constexpr int M_   = B_ * S_;                         // 2048 token rows
constexpr size_t NTOK = (size_t)M_ * DH_;             // 2,097,152
constexpr size_t NSC  = (size_t)B_ * H_ * S_ * S_;    // 33,554,432
}

// Scratch (device globals: no allocations allowed anywhere).
__device__ float g_q[3][NTOK];   // q_s, q_b, q_z
__device__ float g_k[3][NTOK];   // k_s, k_b, k_z
__device__ float g_v[3][NTOK];   // v_s, v_b, v_z
__device__ float g_o[3][NTOK];   // attention outputs ws, wb, wz
__device__ float g_p[3][NTOK];   // ws@Wo+co etc.
__device__ float g_w[3][NSC];    // softmax probabilities

// ---------------------------------------------------------------------------
// Multi-term batched SGEMM:
//   C[2048,1024] = sum_t A_t[2048,K] @ W_t[K,1024] + sum_t bias_t
// One op per blockIdx.z. 128x128 tile, BK=16, 256 threads, 8x8/thread.
// ---------------------------------------------------------------------------
struct GTerm { const float* A; const float* W; const float* bias; };
struct GOp   { GTerm t[3]; float* C; int K; int nt; };
struct GTable { GOp op[9]; };

__global__ void __launch_bounds__(256, 2) gemm_multi(const GTable tab) {
  constexpr int BK = 16;
  constexpr int PA = 132;   // padded pitch for As (k-major)
  __shared__ float As[BK * PA];
  __shared__ float Bs[BK * 128];

  const GOp& op = tab.op[blockIdx.z];
  const int t  = threadIdx.x;
  const int bm = blockIdx.y * 128;
  const int bn = blockIdx.x * 128;
  const int trow = (t >> 4) * 8;
  const int tcol = (t & 15) * 8;
  const int K = op.K;

  float acc[8][8];
#pragma unroll
  for (int i = 0; i < 8; i++)
#pragma unroll
    for (int j = 0; j < 8; j++) acc[i][j] = 0.f;

  for (int tt = 0; tt < op.nt; tt++) {
    const float* __restrict__ A = op.t[tt].A;
    const float* __restrict__ W = op.t[tt].W;
    for (int k0 = 0; k0 < K; k0 += BK) {
#pragma unroll
      for (int i = 0; i < 2; i++) {
        int f  = t + i * 256;
        int ar = f >> 2;            // 0..127
        int ac = (f & 3) * 4;       // 0,4,8,12
        float4 av = *(const float4*)(A + (size_t)(bm + ar) * K + k0 + ac);
        As[(ac + 0) * PA + ar] = av.x;
        As[(ac + 1) * PA + ar] = av.y;
        As[(ac + 2) * PA + ar] = av.z;
        As[(ac + 3) * PA + ar] = av.w;
        int br = f >> 5;            // 0..15
        int bc = (f & 31) * 4;      // 0..124
        *(float4*)(&Bs[br * 128 + bc]) =
            *(const float4*)(W + (size_t)(k0 + br) * DH_ + bn + bc);
      }
      __syncthreads();
#pragma unroll
      for (int kk = 0; kk < BK; kk++) {
        float a[8], b[8];
#pragma unroll
        for (int i = 0; i < 8; i++) a[i] = As[kk * PA + trow + i];
#pragma unroll
        for (int j = 0; j < 8; j++) b[j] = Bs[kk * 128 + tcol + j];
#pragma unroll
        for (int i = 0; i < 8; i++)
#pragma unroll
          for (int j = 0; j < 8; j++) acc[i][j] = fmaf(a[i], b[j], acc[i][j]);
      }
      __syncthreads();
    }
  }

  float bsum[8];
#pragma unroll
  for (int j = 0; j < 8; j++) bsum[j] = 0.f;
  for (int tt = 0; tt < op.nt; tt++)
#pragma unroll
    for (int j = 0; j < 8; j++) bsum[j] += op.t[tt].bias[bn + tcol + j];

  float* __restrict__ C = op.C;
#pragma unroll
  for (int i = 0; i < 8; i++)
#pragma unroll
    for (int j = 0; j < 8; j++)
      C[(size_t)(bm + trow + i) * DH_ + bn + tcol + j] = acc[i][j] + bsum[j];
}

// ---------------------------------------------------------------------------
// Scores (all 3 streams): out[st][b,h,q,k] = sum_d q·k   (raw, no bias)
// grid (S/64, S/64, 3*B*H)
// ---------------------------------------------------------------------------
__global__ void __launch_bounds__(256) scores_kernel(
    const float* __restrict__ qbase, const float* __restrict__ kbase,
    float* __restrict__ outbase) {
  const int zz = blockIdx.z;
  const int st = zz >> 5;
  const int bh = zz & 31;
  const int b  = bh >> 4;
  const int h  = bh & 15;
  const float* q = qbase + (size_t)st * NTOK;
  const float* k = kbase + (size_t)st * NTOK;
  float* out = outbase + (size_t)st * NSC;
  const int q0 = blockIdx.y * 64;
  const int k0 = blockIdx.x * 64;
  __shared__ float Qs[64][65];
  __shared__ float Ks[64][65];
  const int t = threadIdx.x;

#pragma unroll
  for (int i = 0; i < 4; i++) {
    int f   = t + i * 256;
    int row = f >> 4;
    int c   = (f & 15) * 4;
    float4 qv = *(const float4*)(q + (size_t)(b * S_ + q0 + row) * DH_ + h * HD_ + c);
    Qs[row][c + 0] = qv.x; Qs[row][c + 1] = qv.y;
    Qs[row][c + 2] = qv.z; Qs[row][c + 3] = qv.w;
    float4 kv = *(const float4*)(k + (size_t)(b * S_ + k0 + row) * DH_ + h * HD_ + c);
    Ks[row][c + 0] = kv.x; Ks[row][c + 1] = kv.y;
    Ks[row][c + 2] = kv.z; Ks[row][c + 3] = kv.w;
  }
  __syncthreads();

  const int trow = (t >> 4) * 4;
  const int tcol = (t & 15) * 4;
  float acc[4][4];
#pragma unroll
  for (int i = 0; i < 4; i++)
#pragma unroll
    for (int j = 0; j < 4; j++) acc[i][j] = 0.f;

#pragma unroll 16
  for (int d = 0; d < HD_; d++) {
    float a[4], bb[4];
#pragma unroll
    for (int i = 0; i < 4; i++) a[i] = Qs[trow + i][d];
#pragma unroll
    for (int j = 0; j < 4; j++) bb[j] = Ks[tcol + j][d];
#pragma unroll
    for (int i = 0; i < 4; i++)
#pragma unroll
      for (int j = 0; j < 4; j++) acc[i][j] = fmaf(a[i], bb[j], acc[i][j]);
  }

#pragma unroll
  for (int i = 0; i < 4; i++)
#pragma unroll
    for (int j = 0; j < 4; j++)
      out[((size_t)bh * S_ + q0 + trow + i) * S_ + k0 + tcol + j] = acc[i][j];
}

// ---------------------------------------------------------------------------
// Softmax over (scores + bias) for all streams. One block per row.
// grid = 3 * B*H*S rows.
// ---------------------------------------------------------------------------
__global__ void __launch_bounds__(256) softmax_kernel(
    const float* __restrict__ scbase,
    const float* __restrict__ bias0, const float* __restrict__ bias1,
    const float* __restrict__ bias2, float* __restrict__ wbase) {
  const size_t row = blockIdx.x;
  const int st = (int)(row >> 15);                 // 32768 rows per stream
  const size_t lrow = row & 32767;
  const float* bias = (st == 0) ? bias0 : (st == 1) ? bias1 : bias2;
  const float* x  = scbase + (size_t)st * NSC + lrow * S_;
  const float* bi = bias + lrow * S_;
  float* wr = wbase + (size_t)st * NSC + lrow * S_;
  const int t = threadIdx.x;

  float v[4];
  float m = -1e30f;
#pragma unroll
  for (int i = 0; i < 4; i++) {
    v[i] = x[t + i * 256] + bi[t + i * 256];
    m = fmaxf(m, v[i]);
  }
  __shared__ float red[256];
  red[t] = m;
  __syncthreads();
  for (int stp = 128; stp > 0; stp >>= 1) {
    if (t < stp) red[t] = fmaxf(red[t], red[t + stp]);
    __syncthreads();
  }
  const float rowmax = red[0];
  __syncthreads();

  float sum = 0.f;
#pragma unroll
  for (int i = 0; i < 4; i++) {
    v[i] = expf(v[i] - rowmax);
    sum += v[i];
  }
  red[t] = sum;
  __syncthreads();
  for (int stp = 128; stp > 0; stp >>= 1) {
    if (t < stp) red[t] += red[t + stp];
    __syncthreads();
  }
  const float inv = 1.f / red[0];
#pragma unroll
  for (int i = 0; i < 4; i++) wr[t + i * 256] = v[i] * inv;
}

// ---------------------------------------------------------------------------
// Attention output for all streams: o = w @ v_heads
// grid (S/64, 3*B*H)
// ---------------------------------------------------------------------------
__global__ void __launch_bounds__(256) av_kernel(
    const float* __restrict__ wbase, const float* __restrict__ vbase,
    float* __restrict__ obase) {
  const int zz = blockIdx.y;
  const int st = zz >> 5;
  const int bh = zz & 31;
  const int b  = bh >> 4;
  const int h  = bh & 15;
  const float* w = wbase + (size_t)st * NSC;
  const float* v = vbase + (size_t)st * NTOK;
  float* o = obase + (size_t)st * NTOK;
  const int r0 = blockIdx.x * 64;
  __shared__ float Ws[64][17];
  __shared__ float Vs[16][65];
  const int t = threadIdx.x;
  const int trow = (t >> 4) * 4;
  const int tcol = (t & 15) * 4;
  const int wrow = t >> 2;
  const int wc   = (t & 3) * 4;
  const int vrow = t >> 4;
  const int vc   = (t & 15) * 4;

  float acc[4][4];
#pragma unroll
  for (int i = 0; i < 4; i++)
#pragma unroll
    for (int j = 0; j < 4; j++) acc[i][j] = 0.f;

  for (int k0 = 0; k0 < S_; k0 += 16) {
    float4 wv = *(const float4*)(w + ((size_t)bh * S_ + r0 + wrow) * S_ + k0 + wc);
    Ws[wrow][wc + 0] = wv.x; Ws[wrow][wc + 1] = wv.y;
    Ws[wrow][wc + 2] = wv.z; Ws[wrow][wc + 3] = wv.w;
    float4 vv = *(const float4*)(v + (size_t)(b * S_ + k0 + vrow) * DH_ + h * HD_ + vc);
    Vs[vrow][vc + 0] = vv.x; Vs[vrow][vc + 1] = vv.y;
    Vs[vrow][vc + 2] = vv.z; Vs[vrow][vc + 3] = vv.w;
    __syncthreads();
#pragma unroll
    for (int kk = 0; kk < 16; kk++) {
      float a[4], bb[4];
#pragma unroll
      for (int i = 0; i < 4; i++) a[i] = Ws[trow + i][kk];
#pragma unroll
      for (int j = 0; j < 4; j++) bb[j] = Vs[kk][tcol + j];
#pragma unroll
      for (int i = 0; i < 4; i++)
#pragma unroll
        for (int j = 0; j < 4; j++) acc[i][j] = fmaf(a[i], bb[j], acc[i][j]);
    }
    __syncthreads();
  }

#pragma unroll
  for (int i = 0; i < 4; i++)
#pragma unroll
    for (int j = 0; j < 4; j++)
      o[(size_t)(b * S_ + r0 + trow + i) * DH_ + h * HD_ + tcol + j] = acc[i][j];
}

// ---------------------------------------------------------------------------
// Residual chain.
// ---------------------------------------------------------------------------
__global__ void __launch_bounds__(256) combine_kernel(
    const float* __restrict__ s, const float* __restrict__ b,
    const float* __restrict__ z, const float* __restrict__ ps,
    const float* __restrict__ pb, const float* __restrict__ pz,
    float* __restrict__ os, float* __restrict__ ob, float* __restrict__ oz) {
  size_t i = (size_t)blockIdx.x * 256 + threadIdx.x;
  if (i >= NTOK) return;
  float so = s[i] + ps[i];
  float bo = so + b[i] + pb[i];
  float zo = bo + z[i] + pz[i];
  os[i] = so;
  ob[i] = bo;
  oz[i] = zo;
}

// ---------------------------------------------------------------------------
extern "C" void kernel_launch(void* const* d_in, const int* in_sizes, int n_in,
                              void* d_out, int out_size) {
  const float* y    = (const float*)d_in[0];
  const float* s    = (const float*)d_in[1];
  const float* b    = (const float*)d_in[2];
  const float* z    = (const float*)d_in[3];
  const float* ba0  = (const float*)d_in[4];
  const float* ba1  = (const float*)d_in[5];
  const float* ba2  = (const float*)d_in[6];
  const float* Wqs  = (const float*)d_in[7];
  const float* cqs  = (const float*)d_in[8];
  const float* Wqb  = (const float*)d_in[9];
  const float* cqb  = (const float*)d_in[10];
  const float* Wqz  = (const float*)d_in[11];
  const float* cqz  = (const float*)d_in[12];
  const float* Wkss = (const float*)d_in[13];
  const float* ckss = (const float*)d_in[14];
  const float* Wksb = (const float*)d_in[15];
  const float* cksb = (const float*)d_in[16];
  const float* Wkzb = (const float*)d_in[17];
  const float* ckzb = (const float*)d_in[18];
  const float* Wkbb = (const float*)d_in[19];
  const float* ckbb = (const float*)d_in[20];
  const float* Wkzz = (const float*)d_in[21];
  const float* ckzz = (const float*)d_in[22];
  const float* Wvs  = (const float*)d_in[23];
  const float* cvs  = (const float*)d_in[24];
  const float* Wvb  = (const float*)d_in[25];
  const float* cvb  = (const float*)d_in[26];
  const float* Wvz  = (const float*)d_in[27];
  const float* cvz  = (const float*)d_in[28];
  const float* Wo   = (const float*)d_in[29];
  const float* co   = (const float*)d_in[30];

  float* out   = (float*)d_out;
  float* s_out = out;
  float* b_out = out + NTOK;
  float* z_out = out + 2 * NTOK;
  float* scb   = out + 3 * NTOK;   // base of the three score tensors

  float *gq, *gk, *gv, *go, *gp, *gw;
  cudaGetSymbolAddress((void**)&gq, g_q);
  cudaGetSymbolAddress((void**)&gk, g_k);
  cudaGetSymbolAddress((void**)&gv, g_v);
  cudaGetSymbolAddress((void**)&go, g_o);
  cudaGetSymbolAddress((void**)&gp, g_p);
  cudaGetSymbolAddress((void**)&gw, g_w);

  // --- Launch 1: all 9 projection outputs (multi-term fused) ---
  GTable tab{};
  auto setop = [&](int idx, float* C, int K, int nt,
                   const float* A0, const float* W0, const float* c0_,
                   const float* A1 = nullptr, const float* W1 = nullptr, const float* c1_ = nullptr,
                   const float* A2 = nullptr, const float* W2 = nullptr, const float* c2_ = nullptr) {
    tab.op[idx].C = C; tab.op[idx].K = K; tab.op[idx].nt = nt;
    tab.op[idx].t[0] = {A0, W0, c0_};
    tab.op[idx].t[1] = {A1, W1, c1_};
    tab.op[idx].t[2] = {A2, W2, c2_};
  };
  setop(0, gq + 0 * NTOK, DIN_, 1, y, Wqs, cqs);
  setop(1, gq + 1 * NTOK, DIN_, 1, y, Wqb, cqb);
  setop(2, gq + 2 * NTOK, DIN_, 1, y, Wqz, cqz);
  setop(3, gk + 0 * NTOK, DH_, 2, s, Wkss, ckss, b, Wksb, cksb);
  setop(4, gk + 1 * NTOK, DH_, 3, b, Wkbb, ckbb, s, Wksb, cksb, z, Wkzb, ckzb);
  setop(5, gk + 2 * NTOK, DH_, 2, z, Wkzz, ckzz, b, Wkzb, ckzb);
  setop(6, gv + 0 * NTOK, DH_, 1, s, Wvs, cvs);
  setop(7, gv + 1 * NTOK, DH_, 1, b, Wvb, cvb);
  setop(8, gv + 2 * NTOK, DH_, 1, z, Wvz, cvz);

  gemm_multi<<<dim3(DH_ / 128, M_ / 128, 9), 256>>>(tab);

  // --- Launch 2: scores for all 3 streams (raw, into d_out) ---
  scores_kernel<<<dim3(S_ / 64, S_ / 64, 3 * B_ * H_), 256>>>(gq, gk, scb);

  // --- Launch 3: softmax for all 3 streams ---
  softmax_kernel<<<3 * B_ * H_ * S_, 256>>>(scb, ba0, ba1, ba2, gw);

  // --- Launch 4: attention output for all 3 streams ---
  av_kernel<<<dim3(S_ / 64, 3 * B_ * H_), 256>>>(gw, gv, go);

  // --- Launch 5: output projections (3 ops) ---
  GTable tab2{};
  tab2.op[0] = {{{go + 0 * NTOK, Wo, co}, {}, {}}, gp + 0 * NTOK, DH_, 1};
  tab2.op[1] = {{{go + 1 * NTOK, Wo, co}, {}, {}}, gp + 1 * NTOK, DH_, 1};
  tab2.op[2] = {{{go + 2 * NTOK, Wo, co}, {}, {}}, gp + 2 * NTOK, DH_, 1};
  gemm_multi<<<dim3(DH_ / 128, M_ / 128, 3), 256>>>(tab2);

  // --- Launch 6: residual chain ---
  combine_kernel<<<(int)((NTOK + 255) / 256), 256>>>(
      s, b, z, gp + 0 * NTOK, gp + 1 * NTOK, gp + 2 * NTOK,
      s_out, b_out, z_out);
}

// round 4
// speedup vs baseline: 2.6907x; 2.6907x over previous
#include <cuda_runtime.h>
#include <cstdint>
#include <math.h>

// ===========================================================================
// MarkovBlanketAttention on sm_103 (base target) — R3:
// mma.sync.m16n8k8 tf32 tensor cores; 3xTF32 split on the precision-critical
// chain (Q/K projections, QK^T); single tf32 elsewhere.
// B=2, S=1024, DIN=512, DH=1024, H=16, HD=64
// ===========================================================================

namespace {
constexpr int B_   = 2;
constexpr int S_   = 1024;
constexpr int DIN_ = 512;
constexpr int DH_  = 1024;
constexpr int H_   = 16;
constexpr int HD_  = 64;
constexpr int M_   = B_ * S_;
constexpr size_t NTOK = (size_t)M_ * DH_;
constexpr size_t NSC  = (size_t)B_ * H_ * S_ * S_;
}

// ---- scratch (device globals; no allocations allowed) ----
__device__ float g_q[3][NTOK];
__device__ float g_k[3][NTOK];
__device__ float g_v[3][NTOK];
__device__ float g_o[3][NTOK];
__device__ float g_p[3][NTOK];
__device__ float g_w[3][NSC];
__device__ float g_wt[12][DH_ * DH_];   // W^T  [N=1024][K]
__device__ float g_vt[96][HD_ * S_];    // per-(st,b,h) V^T [64][1024]

// ---------------------------------------------------------------------------
// helpers
// ---------------------------------------------------------------------------
__device__ __forceinline__ uint32_t smem_u32(const void* p) {
  uint32_t a;
  asm("{ .reg .u64 t; cvta.to.shared.u64 t, %1; cvt.u32.u64 %0, t; }"
      : "=r"(a) : "l"(p));
  return a;
}
__device__ __forceinline__ void cp16(void* smem, const void* g) {
  asm volatile("cp.async.cg.shared.global [%0], [%1], 16;"
               :: "r"(smem_u32(smem)), "l"(g));
}
__device__ __forceinline__ void cp_commit() {
  asm volatile("cp.async.commit_group;" ::: "memory");
}
template <int N>
__device__ __forceinline__ void cp_wait() {
  asm volatile("cp.async.wait_group %0;" :: "n"(N) : "memory");
}
__device__ __forceinline__ void mma8(float* c, const uint32_t* a,
                                     const uint32_t* b) {
  asm volatile(
      "mma.sync.aligned.m16n8k8.row.col.f32.tf32.tf32.f32 "
      "{%0,%1,%2,%3}, {%4,%5,%6,%7}, {%8,%9}, {%0,%1,%2,%3};"
      : "+f"(c[0]), "+f"(c[1]), "+f"(c[2]), "+f"(c[3])
      : "r"(a[0]), "r"(a[1]), "r"(a[2]), "r"(a[3]), "r"(b[0]), "r"(b[1]));
}
__device__ __forceinline__ uint32_t rn_tf32(float f) {   // RN-ish via +0x1000
  return __float_as_uint(f) + 0x1000u;
}
__device__ __forceinline__ uint32_t hi_tf32(float f) {   // RZ truncation
  return __float_as_uint(f) & 0xFFFFE000u;
}
__device__ __forceinline__ uint32_t lo_tf32(float f, uint32_t hi) {
  return __float_as_uint(f - __uint_as_float(hi));
}

// ---------------------------------------------------------------------------
// Core: C[128 x BN] = sum_terms A_t @ B_t^T (+ sum biases)
// A: rows [m][K] stride lda ; Bmat: rows [n][K] stride ldb (col-major B)
// PRECISE: 3xTF32 split (err ~2^-21); else single tf32 (err ~2^-11).
// ---------------------------------------------------------------------------
struct Term { const float* A; const float* W; const float* bias; };
struct Op   { Term t[3]; float* C; int nt; int K; int lda; int ldb; int ldc; };
struct OpTable { Op op[9]; };

template <int BN, bool PRECISE>
__device__ __forceinline__ void gemm_core(const Op& op) {
  constexpr int BK = 16;
  constexpr int PITCH = 20;                 // floats; 80B rows, 16B-aligned
  constexpr int WN = BN / 2;                // warp n-extent (warps 4x2)
  constexpr int NT = WN / 8;                // 8-wide mma tiles per warp
  __shared__ float As[2][128 * PITCH];
  __shared__ float Bs[2][BN * PITCH];

  const int t = threadIdx.x;
  const int wid = t >> 5, lane = t & 31;
  const int warp_m = wid & 3, warp_n = wid >> 1 & 1 ? 0 : 0; // placeholder
  const int wn = wid >> 2;                  // 0..1
  const int gid = lane >> 2, qid = lane & 3;

  const int bm = blockIdx.y * 128;
  const int bn = blockIdx.x * BN;
  const int cpt = op.K / BK;
  const int total = op.nt * cpt;

  float acc[2][NT][4];
#pragma unroll
  for (int mt = 0; mt < 2; mt++)
#pragma unroll
    for (int nt = 0; nt < NT; nt++)
#pragma unroll
      for (int j = 0; j < 4; j++) acc[mt][nt][j] = 0.f;

  auto load_chunk = [&](int c, int buf) {
    const int term = c / cpt;
    const int k0 = (c - term * cpt) * BK;
    const float* __restrict__ A = op.t[term].A;
    const float* __restrict__ W = op.t[term].W;
#pragma unroll
    for (int i = 0; i < 2; i++) {           // A: 128 rows x 4 float4
      int f = t + i * 256;
      int r = f >> 2, c4 = (f & 3) * 4;
      cp16(&As[buf][r * PITCH + c4], A + (size_t)(bm + r) * op.lda + k0 + c4);
    }
#pragma unroll
    for (int i = 0; i < BN / 64; i++) {     // B: BN rows x 4 float4
      int f = t + i * 256;
      int r = f >> 2, c4 = (f & 3) * 4;
      cp16(&Bs[buf][r * PITCH + c4], W + (size_t)(bn + r) * op.ldb + k0 + c4);
    }
  };

  load_chunk(0, 0);
  cp_commit();

  for (int c = 0; c < total; c++) {
    const int buf = c & 1;
    if (c + 1 < total) load_chunk(c + 1, (c + 1) & 1);
    cp_commit();
    cp_wait<1>();
    __syncthreads();

#pragma unroll
    for (int kk = 0; kk < BK; kk += 8) {
      // ---- A fragments ----
      uint32_t ah[2][4], al[2][4];
#pragma unroll
      for (int mt = 0; mt < 2; mt++) {
        int r0 = warp_m * 32 + mt * 16 + gid;
        float f0 = As[buf][(r0)     * PITCH + kk + qid];
        float f1 = As[buf][(r0 + 8) * PITCH + kk + qid];
        float f2 = As[buf][(r0)     * PITCH + kk + qid + 4];
        float f3 = As[buf][(r0 + 8) * PITCH + kk + qid + 4];
        if (PRECISE) {
          ah[mt][0] = hi_tf32(f0); al[mt][0] = lo_tf32(f0, ah[mt][0]);
          ah[mt][1] = hi_tf32(f1); al[mt][1] = lo_tf32(f1, ah[mt][1]);
          ah[mt][2] = hi_tf32(f2); al[mt][2] = lo_tf32(f2, ah[mt][2]);
          ah[mt][3] = hi_tf32(f3); al[mt][3] = lo_tf32(f3, ah[mt][3]);
        } else {
          ah[mt][0] = rn_tf32(f0); ah[mt][1] = rn_tf32(f1);
          ah[mt][2] = rn_tf32(f2); ah[mt][3] = rn_tf32(f3);
        }
      }
      // ---- B fragments + mma ----
#pragma unroll
      for (int nt = 0; nt < NT; nt++) {
        int n0 = wn * WN + nt * 8 + gid;
        float g0 = Bs[buf][n0 * PITCH + kk + qid];
        float g1 = Bs[buf][n0 * PITCH + kk + qid + 4];
        if (PRECISE) {
          uint32_t bh[2], bl[2];
          bh[0] = hi_tf32(g0); bl[0] = lo_tf32(g0, bh[0]);
          bh[1] = hi_tf32(g1); bl[1] = lo_tf32(g1, bh[1]);
#pragma unroll
          for (int mt = 0; mt < 2; mt++) {
            mma8(acc[mt][nt], ah[mt], bh);
            mma8(acc[mt][nt], ah[mt], bl);
            mma8(acc[mt][nt], al[mt], bh);
          }
        } else {
          uint32_t br[2] = {rn_tf32(g0), rn_tf32(g1)};
#pragma unroll
          for (int mt = 0; mt < 2; mt++) mma8(acc[mt][nt], ah[mt], br);
        }
      }
    }
    __syncthreads();
  }

  // ---- epilogue ----
#pragma unroll
  for (int mt = 0; mt < 2; mt++) {
    int row0 = bm + warp_m * 32 + mt * 16 + gid;
#pragma unroll
    for (int nt = 0; nt < NT; nt++) {
      int col = bn + wn * WN + nt * 8 + qid * 2;
      float b0 = 0.f, b1 = 0.f;
      if (op.t[0].bias) {
        for (int tt = 0; tt < op.nt; tt++) {
          b0 += op.t[tt].bias[col];
          b1 += op.t[tt].bias[col + 1];
        }
      }
      float2 v0 = {acc[mt][nt][0] + b0, acc[mt][nt][1] + b1};
      float2 v1 = {acc[mt][nt][2] + b0, acc[mt][nt][3] + b1};
      *(float2*)(op.C + (size_t)row0 * op.ldc + col) = v0;
      *(float2*)(op.C + (size_t)(row0 + 8) * op.ldc + col) = v1;
    }
  }
  (void)warp_n;
}

// ---------------------------------------------------------------------------
// kernels
// ---------------------------------------------------------------------------
__global__ void __launch_bounds__(256) proj_precise(const OpTable tab) {
  gemm_core<128, true>(tab.op[blockIdx.z]);
}
__global__ void __launch_bounds__(256) proj_fast(const OpTable tab) {
  gemm_core<128, false>(tab.op[blockIdx.z]);
}
__global__ void __launch_bounds__(256) score_mma(const float* q, const float* k,
                                                 float* out) {
  int z = blockIdx.z, st = z >> 5, bh = z & 31, b = bh >> 4, h = bh & 15;
  Op op{};
  op.t[0].A = q + (size_t)st * NTOK + (size_t)b * S_ * DH_ + h * HD_;
  op.t[0].W = k + (size_t)st * NTOK + (size_t)b * S_ * DH_ + h * HD_;
  op.t[0].bias = nullptr;
  op.C = out + (size_t)st * NSC + (size_t)bh * S_ * S_;
  op.nt = 1; op.K = HD_; op.lda = DH_; op.ldb = DH_; op.ldc = S_;
  gemm_core<128, true>(op);
}
__global__ void __launch_bounds__(256) pv_mma(const float* w, const float* vt,
                                              float* o) {
  int z = blockIdx.z, st = z >> 5, bh = z & 31, b = bh >> 4, h = bh & 15;
  Op op{};
  op.t[0].A = w + (size_t)st * NSC + (size_t)bh * S_ * S_;
  op.t[0].W = vt + (size_t)z * HD_ * S_;
  op.t[0].bias = nullptr;
  op.C = o + (size_t)st * NTOK + (size_t)b * S_ * DH_ + h * HD_;
  op.nt = 1; op.K = S_; op.lda = S_; op.ldb = S_; op.ldc = DH_;
  gemm_core<64, false>(op);
}

// ---- transposes ----
struct WEnt { const float* src; float* dst; int K; };
struct WTab { WEnt e[12]; };

__global__ void __launch_bounds__(256) transpose_w(const WTab tab) {
  WEnt e = tab.e[blockIdx.z];
  int n0 = blockIdx.x * 32, k0 = blockIdx.y * 32;
  if (k0 >= e.K) return;
  __shared__ float tl[32][33];
  int tx = threadIdx.x, ty = threadIdx.y;
#pragma unroll
  for (int i = 0; i < 32; i += 8)
    tl[ty + i][tx] = e.src[(size_t)(k0 + ty + i) * DH_ + n0 + tx];
  __syncthreads();
#pragma unroll
  for (int i = 0; i < 32; i += 8)
    e.dst[(size_t)(n0 + ty + i) * e.K + k0 + tx] = tl[tx][ty + i];
}

__global__ void __launch_bounds__(256) transpose_v(const float* v, float* vt) {
  int z = blockIdx.z, st = z >> 5, bh = z & 31, b = bh >> 4, h = bh & 15;
  int c0 = blockIdx.x * 32, k0 = blockIdx.y * 32;
  __shared__ float tl[32][33];
  int tx = threadIdx.x, ty = threadIdx.y;
  const float* src = v + (size_t)st * NTOK + (size_t)b * S_ * DH_ + h * HD_;
  float* dst = vt + (size_t)z * HD_ * S_;
#pragma unroll
  for (int i = 0; i < 32; i += 8)
    tl[ty + i][tx] = src[(size_t)(k0 + ty + i) * DH_ + c0 + tx];
  __syncthreads();
#pragma unroll
  for (int i = 0; i < 32; i += 8)
    dst[(size_t)(c0 + ty + i) * S_ + k0 + tx] = tl[tx][ty + i];
}

// ---- softmax over (scores + bias) ----
__global__ void __launch_bounds__(256) softmax_kernel(
    const float* __restrict__ scbase, const float* __restrict__ bias0,
    const float* __restrict__ bias1, const float* __restrict__ bias2,
    float* __restrict__ wbase) {
  const size_t row = blockIdx.x;
  const int st = (int)(row >> 15);
  const size_t lrow = row & 32767;
  const float* bias = (st == 0) ? bias0 : (st == 1) ? bias1 : bias2;
  const float* x  = scbase + (size_t)st * NSC + lrow * S_;
  const float* bi = bias + lrow * S_;
  float* wr = wbase + (size_t)st * NSC + lrow * S_;
  const int t = threadIdx.x;

  float v[4];
  float m = -1e30f;
#pragma unroll
  for (int i = 0; i < 4; i++) {
    v[i] = x[t + i * 256] + bi[t + i * 256];
    m = fmaxf(m, v[i]);
  }
  __shared__ float red[256];
  red[t] = m;
  __syncthreads();
  for (int stp = 128; stp > 0; stp >>= 1) {
    if (t < stp) red[t] = fmaxf(red[t], red[t + stp]);
    __syncthreads();
  }
  const float rowmax = red[0];
  __syncthreads();
  float sum = 0.f;
#pragma unroll
  for (int i = 0; i < 4; i++) { v[i] = expf(v[i] - rowmax); sum += v[i]; }
  red[t] = sum;
  __syncthreads();
  for (int stp = 128; stp > 0; stp >>= 1) {
    if (t < stp) red[t] += red[t + stp];
    __syncthreads();
  }
  const float inv = 1.f / red[0];
#pragma unroll
  for (int i = 0; i < 4; i++) wr[t + i * 256] = v[i] * inv;
}

// ---- residual chain ----
__global__ void __launch_bounds__(256) combine_kernel(
    const float* __restrict__ s, const float* __restrict__ b,
    const float* __restrict__ z, const float* __restrict__ ps,
    const float* __restrict__ pb, const float* __restrict__ pz,
    float* __restrict__ os, float* __restrict__ ob, float* __restrict__ oz) {
  size_t i = (size_t)blockIdx.x * 256 + threadIdx.x;
  if (i >= NTOK) return;
  float so = s[i] + ps[i];
  float bo = so + b[i] + pb[i];
  float zo = bo + z[i] + pz[i];
  os[i] = so; ob[i] = bo; oz[i] = zo;
}

// ===========================================================================
extern "C" void kernel_launch(void* const* d_in, const int* in_sizes, int n_in,
                              void* d_out, int out_size) {
  const float* y    = (const float*)d_in[0];
  const float* s    = (const float*)d_in[1];
  const float* b    = (const float*)d_in[2];
  const float* z    = (const float*)d_in[3];
  const float* ba0  = (const float*)d_in[4];
  const float* ba1  = (const float*)d_in[5];
  const float* ba2  = (const float*)d_in[6];
  const float* W[12] = {
      (const float*)d_in[7],  (const float*)d_in[9],  (const float*)d_in[11],
      (const float*)d_in[13], (const float*)d_in[15], (const float*)d_in[17],
      (const float*)d_in[19], (const float*)d_in[21],
      (const float*)d_in[23], (const float*)d_in[25], (const float*)d_in[27],
      (const float*)d_in[29]};
  const float* C[12] = {
      (const float*)d_in[8],  (const float*)d_in[10], (const float*)d_in[12],
      (const float*)d_in[14], (const float*)d_in[16], (const float*)d_in[18],
      (const float*)d_in[20], (const float*)d_in[22],
      (const float*)d_in[24], (const float*)d_in[26], (const float*)d_in[28],
      (const float*)d_in[30]};
  const int KW[12] = {DIN_, DIN_, DIN_, DH_, DH_, DH_, DH_, DH_,
                      DH_, DH_, DH_, DH_};

  float* out   = (float*)d_out;
  float* s_out = out;
  float* b_out = out + NTOK;
  float* z_out = out + 2 * NTOK;
  float* scb   = out + 3 * NTOK;

  float *gq, *gk, *gv, *go, *gp, *gw, *gwt, *gvt;
  cudaGetSymbolAddress((void**)&gq, g_q);
  cudaGetSymbolAddress((void**)&gk, g_k);
  cudaGetSymbolAddress((void**)&gv, g_v);
  cudaGetSymbolAddress((void**)&go, g_o);
  cudaGetSymbolAddress((void**)&gp, g_p);
  cudaGetSymbolAddress((void**)&gw, g_w);
  cudaGetSymbolAddress((void**)&gwt, g_wt);
  cudaGetSymbolAddress((void**)&gvt, g_vt);

  // --- 1: transpose all weights -> g_wt[i] = W[i]^T ([1024][K]) ---
  WTab wt{};
  for (int i = 0; i < 12; i++)
    wt.e[i] = {W[i], gwt + (size_t)i * DH_ * DH_, KW[i]};
  transpose_w<<<dim3(32, 32, 12), dim3(32, 8)>>>(wt);

  auto WT = [&](int i) -> const float* { return gwt + (size_t)i * DH_ * DH_; };

  // weight indices: 0 qs 1 qb 2 qz 3 kss 4 ksb 5 kzb 6 kbb 7 kzz 8 vs 9 vb 10 vz 11 o
  auto setop = [&](OpTable& tb, int idx, float* Cp, int K, int nt,
                   const float* A0, int w0,
                   const float* A1 = nullptr, int w1 = -1,
                   const float* A2 = nullptr, int w2 = -1) {
    Op& o = tb.op[idx];
    o.C = Cp; o.K = K; o.nt = nt; o.lda = K; o.ldb = K; o.ldc = DH_;
    o.t[0] = {A0, WT(w0), C[w0]};
    if (nt > 1) o.t[1] = {A1, WT(w1), C[w1]};
    if (nt > 2) o.t[2] = {A2, WT(w2), C[w2]};
  };

  // --- 2a: Q + K projections (precise, 6 ops) ---
  OpTable tqk{};
  setop(tqk, 0, gq + 0 * NTOK, DIN_, 1, y, 0);
  setop(tqk, 1, gq + 1 * NTOK, DIN_, 1, y, 1);
  setop(tqk, 2, gq + 2 * NTOK, DIN_, 1, y, 2);
  setop(tqk, 3, gk + 0 * NTOK, DH_, 2, s, 3, b, 4);
  setop(tqk, 4, gk + 1 * NTOK, DH_, 3, b, 6, s, 4, z, 5);
  setop(tqk, 5, gk + 2 * NTOK, DH_, 2, z, 7, b, 5);
  proj_precise<<<dim3(8, 16, 6), 256>>>(tqk);

  // --- 2b: V projections (fast, 3 ops) ---
  OpTable tv{};
  setop(tv, 0, gv + 0 * NTOK, DH_, 1, s, 8);
  setop(tv, 1, gv + 1 * NTOK, DH_, 1, b, 9);
  setop(tv, 2, gv + 2 * NTOK, DH_, 1, z, 10);
  proj_fast<<<dim3(8, 16, 3), 256>>>(tv);

  // --- 3: V transpose ---
  transpose_v<<<dim3(2, 32, 96), dim3(32, 8)>>>(gv, gvt);

  // --- 4: scores (precise, raw, straight into d_out) ---
  score_mma<<<dim3(8, 8, 96), 256>>>(gq, gk, scb);

  // --- 5: softmax ---
  softmax_kernel<<<3 * B_ * H_ * S_, 256>>>(scb, ba0, ba1, ba2, gw);

  // --- 6: P @ V (fast) ---
  pv_mma<<<dim3(1, 8, 96), 256>>>(gw, gvt, go);

  // --- 7: output projections (fast) ---
  OpTable to{};
  for (int i = 0; i < 3; i++)
    setop(to, i, gp + (size_t)i * NTOK, DH_, 1, go + (size_t)i * NTOK, 11);
  proj_fast<<<dim3(8, 16, 3), 256>>>(to);

  // --- 8: residual chain ---
  combine_kernel<<<(int)((NTOK + 255) / 256), 256>>>(
      s, b, z, gp + 0 * NTOK, gp + 1 * NTOK, gp + 2 * NTOK,
      s_out, b_out, z_out);
}

// round 5
// speedup vs baseline: 3.0950x; 1.1503x over previous
#include <cuda_runtime.h>
#include <cuda_bf16.h>
#include <cstdint>
#include <math.h>

// ===========================================================================
// MarkovBlanketAttention on sm_103 — R4:
// Precise chain (Q/K proj, QK^T) via packed-bf16x2 split: 2x m16n8k16 bf16
// MMAs replace 3x m16n8k8 tf32 MMAs (same addressing, ~2^-17 accuracy).
// Fast chain (V proj, PV, out proj) stays single-pass tf32.
// ===========================================================================

namespace {
constexpr int B_   = 2;
constexpr int S_   = 1024;
constexpr int DIN_ = 512;
constexpr int DH_  = 1024;
constexpr int H_   = 16;
constexpr int HD_  = 64;
constexpr int M_   = B_ * S_;
constexpr size_t NTOK = (size_t)M_ * DH_;
constexpr size_t NSC  = (size_t)B_ * H_ * S_ * S_;
}

// ---- scratch (device globals) ----
__device__ uint32_t g_q[3][NTOK];        // packed bf16x2 Q
__device__ uint32_t g_k[3][NTOK];        // packed bf16x2 K
__device__ float    g_v[3][NTOK];
__device__ float    g_o[3][NTOK];
__device__ float    g_p[3][NTOK];
__device__ float    g_w[3][NSC];
__device__ float    g_wt[12][DH_ * DH_]; // W^T; indices 0..7 hold packed bits
__device__ float    g_vt[96][HD_ * S_];
__device__ uint32_t g_ypk[M_ * DIN_];    // packed inputs
__device__ uint32_t g_spk[M_ * DH_];
__device__ uint32_t g_bpk[M_ * DH_];
__device__ uint32_t g_zpk[M_ * DH_];

// ---------------------------------------------------------------------------
// helpers
// ---------------------------------------------------------------------------
__device__ __forceinline__ uint32_t smem_u32(const void* p) {
  uint32_t a;
  asm("{ .reg .u64 t; cvta.to.shared.u64 t, %1; cvt.u32.u64 %0, t; }"
      : "=r"(a) : "l"(p));
  return a;
}
__device__ __forceinline__ void cp16(void* smem, const void* g) {
  asm volatile("cp.async.cg.shared.global [%0], [%1], 16;"
               :: "r"(smem_u32(smem)), "l"(g));
}
__device__ __forceinline__ void cp_commit() {
  asm volatile("cp.async.commit_group;" ::: "memory");
}
template <int N>
__device__ __forceinline__ void cp_wait() {
  asm volatile("cp.async.wait_group %0;" :: "n"(N) : "memory");
}
__device__ __forceinline__ void mma_tf32_k8(float* c, const uint32_t* a,
                                            const uint32_t* b) {
  asm volatile(
      "mma.sync.aligned.m16n8k8.row.col.f32.tf32.tf32.f32 "
      "{%0,%1,%2,%3}, {%4,%5,%6,%7}, {%8,%9}, {%0,%1,%2,%3};"
      : "+f"(c[0]), "+f"(c[1]), "+f"(c[2]), "+f"(c[3])
      : "r"(a[0]), "r"(a[1]), "r"(a[2]), "r"(a[3]), "r"(b[0]), "r"(b[1]));
}
__device__ __forceinline__ void mma_bf16_k16(float* c, const uint32_t* a,
                                             const uint32_t* b) {
  asm volatile(
      "mma.sync.aligned.m16n8k16.row.col.f32.bf16.bf16.f32 "
      "{%0,%1,%2,%3}, {%4,%5,%6,%7}, {%8,%9}, {%0,%1,%2,%3};"
      : "+f"(c[0]), "+f"(c[1]), "+f"(c[2]), "+f"(c[3])
      : "r"(a[0]), "r"(a[1]), "r"(a[2]), "r"(a[3]), "r"(b[0]), "r"(b[1]));
}
// pack float -> (bf16 hi in low16, bf16 lo in high16)
__device__ __forceinline__ uint32_t pack_bf2(float v) {
  __nv_bfloat16 h = __float2bfloat16_rn(v);
  float fh = __bfloat162float(h);
  __nv_bfloat16 l = __float2bfloat16_rn(v - fh);
  return (uint32_t)__bfloat16_as_ushort(h) |
         ((uint32_t)__bfloat16_as_ushort(l) << 16);
}

// ---------------------------------------------------------------------------
// Core: C[128 x BN] = sum_terms A_t @ B_t^T (+ sum biases)
// PRECISE: operands pre-packed bf16x2 words; 2x k16 bf16 mma per 8 true-k.
// else: fp32 operands, single tf32 k8 mma per 8 k.
// PACKOUT: epilogue writes packed bf16x2 (for Q/K).
// ---------------------------------------------------------------------------
struct Term { const float* A; const float* W; const float* bias; };
struct Op   { Term t[3]; float* C; int nt; int K; int lda; int ldb; int ldc; };
struct OpTable { Op op[9]; };

template <int BN, bool PRECISE, bool PACKOUT>
__device__ __forceinline__ void gemm_core(const Op& op) {
  constexpr int BK = 16;                    // words (= true k)
  constexpr int PITCH = 20;
  constexpr int WN = BN / 2;
  constexpr int NT = WN / 8;
  __shared__ uint32_t As[2][128 * PITCH];
  __shared__ uint32_t Bs[2][BN * PITCH];

  const int t = threadIdx.x;
  const int wid = t >> 5, lane = t & 31;
  const int warp_m = wid & 3;
  const int wn = wid >> 2;
  const int gid = lane >> 2, qid = lane & 3;

  const int bm = blockIdx.y * 128;
  const int bn = blockIdx.x * BN;
  const int cpt = op.K / BK;
  const int total = op.nt * cpt;

  float acc[2][NT][4];
#pragma unroll
  for (int mt = 0; mt < 2; mt++)
#pragma unroll
    for (int nt = 0; nt < NT; nt++)
#pragma unroll
      for (int j = 0; j < 4; j++) acc[mt][nt][j] = 0.f;

  auto load_chunk = [&](int c, int buf) {
    const int term = c / cpt;
    const int k0 = (c - term * cpt) * BK;
    const float* __restrict__ A = op.t[term].A;
    const float* __restrict__ W = op.t[term].W;
#pragma unroll
    for (int i = 0; i < 2; i++) {
      int f = t + i * 256;
      int r = f >> 2, c4 = (f & 3) * 4;
      cp16(&As[buf][r * PITCH + c4], A + (size_t)(bm + r) * op.lda + k0 + c4);
    }
#pragma unroll
    for (int i = 0; i < BN / 64; i++) {
      int f = t + i * 256;
      int r = f >> 2, c4 = (f & 3) * 4;
      cp16(&Bs[buf][r * PITCH + c4], W + (size_t)(bn + r) * op.ldb + k0 + c4);
    }
  };

  load_chunk(0, 0);
  cp_commit();

  for (int c = 0; c < total; c++) {
    const int buf = c & 1;
    if (c + 1 < total) load_chunk(c + 1, (c + 1) & 1);
    cp_commit();
    cp_wait<1>();
    __syncthreads();

#pragma unroll
    for (int kk = 0; kk < BK; kk += 8) {
      uint32_t af[2][4];
#pragma unroll
      for (int mt = 0; mt < 2; mt++) {
        int r0 = warp_m * 32 + mt * 16 + gid;
        uint32_t w0 = As[buf][(r0)     * PITCH + kk + qid];
        uint32_t w1 = As[buf][(r0 + 8) * PITCH + kk + qid];
        uint32_t w2 = As[buf][(r0)     * PITCH + kk + qid + 4];
        uint32_t w3 = As[buf][(r0 + 8) * PITCH + kk + qid + 4];
        if (PRECISE) {
          af[mt][0] = w0; af[mt][1] = w1; af[mt][2] = w2; af[mt][3] = w3;
        } else {
          af[mt][0] = w0 + 0x1000u; af[mt][1] = w1 + 0x1000u;
          af[mt][2] = w2 + 0x1000u; af[mt][3] = w3 + 0x1000u;
        }
      }
#pragma unroll
      for (int nt = 0; nt < NT; nt++) {
        int n0 = wn * WN + nt * 8 + gid;
        uint32_t u0 = Bs[buf][n0 * PITCH + kk + qid];
        uint32_t u1 = Bs[buf][n0 * PITCH + kk + qid + 4];
        if (PRECISE) {
          uint32_t bh[2] = {__byte_perm(u0, 0, 0x1010),
                            __byte_perm(u1, 0, 0x1010)};
          uint32_t bl[2] = {__byte_perm(u0, 0, 0x3232),
                            __byte_perm(u1, 0, 0x3232)};
#pragma unroll
          for (int mt = 0; mt < 2; mt++) {
            mma_bf16_k16(acc[mt][nt], af[mt], bh);
            mma_bf16_k16(acc[mt][nt], af[mt], bl);
          }
        } else {
          uint32_t br[2] = {u0 + 0x1000u, u1 + 0x1000u};
#pragma unroll
          for (int mt = 0; mt < 2; mt++) mma_tf32_k8(acc[mt][nt], af[mt], br);
        }
      }
    }
    __syncthreads();
  }

  // ---- epilogue ----
#pragma unroll
  for (int mt = 0; mt < 2; mt++) {
    int row0 = bm + warp_m * 32 + mt * 16 + gid;
#pragma unroll
    for (int nt = 0; nt < NT; nt++) {
      int col = bn + wn * WN + nt * 8 + qid * 2;
      float b0 = 0.f, b1 = 0.f;
      if (op.t[0].bias) {
        for (int tt = 0; tt < op.nt; tt++) {
          b0 += op.t[tt].bias[col];
          b1 += op.t[tt].bias[col + 1];
        }
      }
      float v00 = acc[mt][nt][0] + b0, v01 = acc[mt][nt][1] + b1;
      float v10 = acc[mt][nt][2] + b0, v11 = acc[mt][nt][3] + b1;
      if (PACKOUT) {
        uint32_t* Cp = (uint32_t*)op.C;
        uint2 p0 = {pack_bf2(v00), pack_bf2(v01)};
        uint2 p1 = {pack_bf2(v10), pack_bf2(v11)};
        *(uint2*)(Cp + (size_t)row0 * op.ldc + col) = p0;
        *(uint2*)(Cp + (size_t)(row0 + 8) * op.ldc + col) = p1;
      } else {
        float2 p0 = {v00, v01};
        float2 p1 = {v10, v11};
        *(float2*)(op.C + (size_t)row0 * op.ldc + col) = p0;
        *(float2*)(op.C + (size_t)(row0 + 8) * op.ldc + col) = p1;
      }
    }
  }
}

// ---------------------------------------------------------------------------
// kernels
// ---------------------------------------------------------------------------
__global__ void __launch_bounds__(256) proj_precise(const OpTable tab) {
  gemm_core<128, true, true>(tab.op[blockIdx.z]);
}
__global__ void __launch_bounds__(256) proj_fast(const OpTable tab) {
  gemm_core<128, false, false>(tab.op[blockIdx.z]);
}
__global__ void __launch_bounds__(256) score_mma(const uint32_t* q,
                                                 const uint32_t* k,
                                                 float* out) {
  int z = blockIdx.z, st = z >> 5, bh = z & 31, b = bh >> 4, h = bh & 15;
  Op op{};
  op.t[0].A = (const float*)(q + (size_t)st * NTOK + (size_t)b * S_ * DH_ + h * HD_);
  op.t[0].W = (const float*)(k + (size_t)st * NTOK + (size_t)b * S_ * DH_ + h * HD_);
  op.t[0].bias = nullptr;
  op.C = out + (size_t)st * NSC + (size_t)bh * S_ * S_;
  op.nt = 1; op.K = HD_; op.lda = DH_; op.ldb = DH_; op.ldc = S_;
  gemm_core<128, true, false>(op);
}
__global__ void __launch_bounds__(256) pv_mma(const float* w, const float* vt,
                                              float* o) {
  int z = blockIdx.z, st = z >> 5, bh = z & 31, b = bh >> 4, h = bh & 15;
  Op op{};
  op.t[0].A = w + (size_t)st * NSC + (size_t)bh * S_ * S_;
  op.t[0].W = vt + (size_t)z * HD_ * S_;
  op.t[0].bias = nullptr;
  op.C = o + (size_t)st * NTOK + (size_t)b * S_ * DH_ + h * HD_;
  op.nt = 1; op.K = S_; op.lda = S_; op.ldb = S_; op.ldc = DH_;
  gemm_core<64, false, false>(op);
}

// ---- input packing ----
__global__ void __launch_bounds__(256) pack_inputs(const float* __restrict__ src,
                                                   uint32_t* __restrict__ dst,
                                                   int n) {
  int i = blockIdx.x * 256 + threadIdx.x;
  if (i < n) dst[i] = pack_bf2(src[i]);
}

// ---- transposes ----
struct WEnt { const float* src; float* dst; int K; int pack; };
struct WTab { WEnt e[12]; };

__global__ void __launch_bounds__(256) transpose_w(const WTab tab) {
  WEnt e = tab.e[blockIdx.z];
  int n0 = blockIdx.x * 32, k0 = blockIdx.y * 32;
  if (k0 >= e.K) return;
  __shared__ float tl[32][33];
  int tx = threadIdx.x, ty = threadIdx.y;
#pragma unroll
  for (int i = 0; i < 32; i += 8)
    tl[ty + i][tx] = e.src[(size_t)(k0 + ty + i) * DH_ + n0 + tx];
  __syncthreads();
#pragma unroll
  for (int i = 0; i < 32; i += 8) {
    float v = tl[tx][ty + i];
    if (e.pack) v = __uint_as_float(pack_bf2(v));
    e.dst[(size_t)(n0 + ty + i) * e.K + k0 + tx] = v;
  }
}

__global__ void __launch_bounds__(256) transpose_v(const float* v, float* vt) {
  int z = blockIdx.z, st = z >> 5, bh = z & 31, b = bh >> 4, h = bh & 15;
  int c0 = blockIdx.x * 32, k0 = blockIdx.y * 32;
  __shared__ float tl[32][33];
  int tx = threadIdx.x, ty = threadIdx.y;
  const float* src = v + (size_t)st * NTOK + (size_t)b * S_ * DH_ + h * HD_;
  float* dst = vt + (size_t)z * HD_ * S_;
#pragma unroll
  for (int i = 0; i < 32; i += 8)
    tl[ty + i][tx] = src[(size_t)(k0 + ty + i) * DH_ + c0 + tx];
  __syncthreads();
#pragma unroll
  for (int i = 0; i < 32; i += 8)
    dst[(size_t)(c0 + ty + i) * S_ + k0 + tx] = tl[tx][ty + i];
}

// ---- softmax over (scores + bias) ----
__global__ void __launch_bounds__(256) softmax_kernel(
    const float* __restrict__ scbase, const float* __restrict__ bias0,
    const float* __restrict__ bias1, const float* __restrict__ bias2,
    float* __restrict__ wbase) {
  const size_t row = blockIdx.x;
  const int st = (int)(row >> 15);
  const size_t lrow = row & 32767;
  const float* bias = (st == 0) ? bias0 : (st == 1) ? bias1 : bias2;
  const float4* x  = (const float4*)(scbase + (size_t)st * NSC + lrow * S_);
  const float4* bi = (const float4*)(bias + lrow * S_);
  float4* wr = (float4*)(wbase + (size_t)st * NSC + lrow * S_);
  const int t = threadIdx.x;

  float4 xv = x[t], bv = bi[t];
  float v[4] = {xv.x + bv.x, xv.y + bv.y, xv.z + bv.z, xv.w + bv.w};
  float m = fmaxf(fmaxf(v[0], v[1]), fmaxf(v[2], v[3]));
  __shared__ float red[256];
  red[t] = m;
  __syncthreads();
  for (int stp = 128; stp > 0; stp >>= 1) {
    if (t < stp) red[t] = fmaxf(red[t], red[t + stp]);
    __syncthreads();
  }
  const float rowmax = red[0];
  __syncthreads();
  float sum = 0.f;
#pragma unroll
  for (int i = 0; i < 4; i++) { v[i] = expf(v[i] - rowmax); sum += v[i]; }
  red[t] = sum;
  __syncthreads();
  for (int stp = 128; stp > 0; stp >>= 1) {
    if (t < stp) red[t] += red[t + stp];
    __syncthreads();
  }
  const float inv = 1.f / red[0];
  float4 o4 = {v[0] * inv, v[1] * inv, v[2] * inv, v[3] * inv};
  wr[t] = o4;
}

// ---- residual chain ----
__global__ void __launch_bounds__(256) combine_kernel(
    const float* __restrict__ s, const float* __restrict__ b,
    const float* __restrict__ z, const float* __restrict__ ps,
    const float* __restrict__ pb, const float* __restrict__ pz,
    float* __restrict__ os, float* __restrict__ ob, float* __restrict__ oz) {
  size_t i = (size_t)blockIdx.x * 256 + threadIdx.x;
  if (i >= NTOK) return;
  float so = s[i] + ps[i];
  float bo = so + b[i] + pb[i];
  float zo = bo + z[i] + pz[i];
  os[i] = so; ob[i] = bo; oz[i] = zo;
}

// ===========================================================================
extern "C" void kernel_launch(void* const* d_in, const int* in_sizes, int n_in,
                              void* d_out, int out_size) {
  const float* y    = (const float*)d_in[0];
  const float* s    = (const float*)d_in[1];
  const float* b    = (const float*)d_in[2];
  const float* z    = (const float*)d_in[3];
  const float* ba0  = (const float*)d_in[4];
  const float* ba1  = (const float*)d_in[5];
  const float* ba2  = (const float*)d_in[6];
  const float* W[12] = {
      (const float*)d_in[7],  (const float*)d_in[9],  (const float*)d_in[11],
      (const float*)d_in[13], (const float*)d_in[15], (const float*)d_in[17],
      (const float*)d_in[19], (const float*)d_in[21],
      (const float*)d_in[23], (const float*)d_in[25], (const float*)d_in[27],
      (const float*)d_in[29]};
  const float* C[12] = {
      (const float*)d_in[8],  (const float*)d_in[10], (const float*)d_in[12],
      (const float*)d_in[14], (const float*)d_in[16], (const float*)d_in[18],
      (const float*)d_in[20], (const float*)d_in[22],
      (const float*)d_in[24], (const float*)d_in[26], (const float*)d_in[28],
      (const float*)d_in[30]};
  const int KW[12] = {DIN_, DIN_, DIN_, DH_, DH_, DH_, DH_, DH_,
                      DH_, DH_, DH_, DH_};

  float* out   = (float*)d_out;
  float* s_out = out;
  float* b_out = out + NTOK;
  float* z_out = out + 2 * NTOK;
  float* scb   = out + 3 * NTOK;

  uint32_t *gq, *gk, *gyp, *gsp, *gbp, *gzp;
  float *gv, *go, *gp, *gw, *gwt, *gvt;
  cudaGetSymbolAddress((void**)&gq, g_q);
  cudaGetSymbolAddress((void**)&gk, g_k);
  cudaGetSymbolAddress((void**)&gv, g_v);
  cudaGetSymbolAddress((void**)&go, g_o);
  cudaGetSymbolAddress((void**)&gp, g_p);
  cudaGetSymbolAddress((void**)&gw, g_w);
  cudaGetSymbolAddress((void**)&gwt, g_wt);
  cudaGetSymbolAddress((void**)&gvt, g_vt);
  cudaGetSymbolAddress((void**)&gyp, g_ypk);
  cudaGetSymbolAddress((void**)&gsp, g_spk);
  cudaGetSymbolAddress((void**)&gbp, g_bpk);
  cudaGetSymbolAddress((void**)&gzp, g_zpk);

  // --- 1a: pack inputs to bf16x2 ---
  pack_inputs<<<(M_ * DIN_ + 255) / 256, 256>>>(y, gyp, M_ * DIN_);
  pack_inputs<<<(M_ * DH_ + 255) / 256, 256>>>(s, gsp, M_ * DH_);
  pack_inputs<<<(M_ * DH_ + 255) / 256, 256>>>(b, gbp, M_ * DH_);
  pack_inputs<<<(M_ * DH_ + 255) / 256, 256>>>(z, gzp, M_ * DH_);

  // --- 1b: transpose weights (pack precise ones: indices 0..7) ---
  WTab wt{};
  for (int i = 0; i < 12; i++)
    wt.e[i] = {W[i], gwt + (size_t)i * DH_ * DH_, KW[i], i < 8 ? 1 : 0};
  transpose_w<<<dim3(32, 32, 12), dim3(32, 8)>>>(wt);

  auto WT = [&](int i) -> const float* { return gwt + (size_t)i * DH_ * DH_; };

  // weight idx: 0 qs 1 qb 2 qz 3 kss 4 ksb 5 kzb 6 kbb 7 kzz 8 vs 9 vb 10 vz 11 o
  auto setop = [&](OpTable& tb, int idx, float* Cp, int K, int nt,
                   const float* A0, int w0,
                   const float* A1 = nullptr, int w1 = -1,
                   const float* A2 = nullptr, int w2 = -1) {
    Op& o = tb.op[idx];
    o.C = Cp; o.K = K; o.nt = nt; o.lda = K; o.ldb = K; o.ldc = DH_;
    o.t[0] = {A0, WT(w0), C[w0]};
    if (nt > 1) o.t[1] = {A1, WT(w1), C[w1]};
    if (nt > 2) o.t[2] = {A2, WT(w2), C[w2]};
  };

  const float* yp = (const float*)gyp;
  const float* sp = (const float*)gsp;
  const float* bp = (const float*)gbp;
  const float* zp = (const float*)gzp;

  // --- 2a: Q + K projections (precise, packed output) ---
  OpTable tqk{};
  setop(tqk, 0, (float*)(gq + 0 * NTOK), DIN_, 1, yp, 0);
  setop(tqk, 1, (float*)(gq + 1 * NTOK), DIN_, 1, yp, 1);
  setop(tqk, 2, (float*)(gq + 2 * NTOK), DIN_, 1, yp, 2);
  setop(tqk, 3, (float*)(gk + 0 * NTOK), DH_, 2, sp, 3, bp, 4);
  setop(tqk, 4, (float*)(gk + 1 * NTOK), DH_, 3, bp, 6, sp, 4, zp, 5);
  setop(tqk, 5, (float*)(gk + 2 * NTOK), DH_, 2, zp, 7, bp, 5);
  proj_precise<<<dim3(8, 16, 6), 256>>>(tqk);

  // --- 2b: V projections (fast tf32, fp32 operands) ---
  OpTable tv{};
  setop(tv, 0, gv + 0 * NTOK, DH_, 1, s, 8);
  setop(tv, 1, gv + 1 * NTOK, DH_, 1, b, 9);
  setop(tv, 2, gv + 2 * NTOK, DH_, 1, z, 10);
  proj_fast<<<dim3(8, 16, 3), 256>>>(tv);

  // --- 3: V transpose ---
  transpose_v<<<dim3(2, 32, 96), dim3(32, 8)>>>(gv, gvt);

  // --- 4: scores (precise, packed q/k, raw fp32 into d_out) ---
  score_mma<<<dim3(8, 8, 96), 256>>>(gq, gk, scb);

  // --- 5: softmax ---
  softmax_kernel<<<3 * B_ * H_ * S_, 256>>>(scb, ba0, ba1, ba2, gw);

  // --- 6: P @ V (fast tf32) ---
  pv_mma<<<dim3(1, 8, 96), 256>>>(gw, gvt, go);

  // --- 7: output projections (fast tf32) ---
  OpTable to{};
  for (int i = 0; i < 3; i++)
    setop(to, i, gp + (size_t)i * NTOK, DH_, 1, go + (size_t)i * NTOK, 11);
  proj_fast<<<dim3(8, 16, 3), 256>>>(to);

  // --- 8: residual chain ---
  combine_kernel<<<(int)((NTOK + 255) / 256), 256>>>(
      s, b, z, gp + 0 * NTOK, gp + 1 * NTOK, gp + 2 * NTOK,
      s_out, b_out, z_out);
}

// round 6
// speedup vs baseline: 3.2105x; 1.0373x over previous
#include <cuda_runtime.h>
#include <cuda_bf16.h>
#include <cstdint>
#include <math.h>

// ===========================================================================
// MarkovBlanketAttention on sm_103 — R5:
// Flash-style fused scores+softmax+PV (online softmax, raw scores streamed to
// d_out). Projections unchanged from R4 (packed-bf16x2 2-MMA precise chain,
// tf32 fast chain).
// ===========================================================================

namespace {
constexpr int B_   = 2;
constexpr int S_   = 1024;
constexpr int DIN_ = 512;
constexpr int DH_  = 1024;
constexpr int H_   = 16;
constexpr int HD_  = 64;
constexpr int M_   = B_ * S_;
constexpr size_t NTOK = (size_t)M_ * DH_;
constexpr size_t NSC  = (size_t)B_ * H_ * S_ * S_;
}

// ---- scratch (device globals) ----
__device__ uint32_t g_q[3][NTOK];        // packed bf16x2 Q
__device__ uint32_t g_k[3][NTOK];        // packed bf16x2 K
__device__ float    g_v[3][NTOK];
__device__ float    g_o[3][NTOK];
__device__ float    g_p[3][NTOK];
__device__ float    g_wt[12][DH_ * DH_]; // W^T; indices 0..7 hold packed bits
__device__ uint32_t g_ypk[M_ * DIN_];    // packed inputs
__device__ uint32_t g_spk[M_ * DH_];
__device__ uint32_t g_bpk[M_ * DH_];
__device__ uint32_t g_zpk[M_ * DH_];

// ---------------------------------------------------------------------------
// helpers
// ---------------------------------------------------------------------------
__device__ __forceinline__ uint32_t smem_u32(const void* p) {
  uint32_t a;
  asm("{ .reg .u64 t; cvta.to.shared.u64 t, %1; cvt.u32.u64 %0, t; }"
      : "=r"(a) : "l"(p));
  return a;
}
__device__ __forceinline__ void cp16(void* smem, const void* g) {
  asm volatile("cp.async.cg.shared.global [%0], [%1], 16;"
               :: "r"(smem_u32(smem)), "l"(g));
}
__device__ __forceinline__ void cp_commit() {
  asm volatile("cp.async.commit_group;" ::: "memory");
}
template <int N>
__device__ __forceinline__ void cp_wait() {
  asm volatile("cp.async.wait_group %0;" :: "n"(N) : "memory");
}
__device__ __forceinline__ void mma_tf32_k8(float* c, const uint32_t* a,
                                            const uint32_t* b) {
  asm volatile(
      "mma.sync.aligned.m16n8k8.row.col.f32.tf32.tf32.f32 "
      "{%0,%1,%2,%3}, {%4,%5,%6,%7}, {%8,%9}, {%0,%1,%2,%3};"
      : "+f"(c[0]), "+f"(c[1]), "+f"(c[2]), "+f"(c[3])
      : "r"(a[0]), "r"(a[1]), "r"(a[2]), "r"(a[3]), "r"(b[0]), "r"(b[1]));
}
__device__ __forceinline__ void mma_bf16_k16(float* c, const uint32_t* a,
                                             const uint32_t* b) {
  asm volatile(
      "mma.sync.aligned.m16n8k16.row.col.f32.bf16.bf16.f32 "
      "{%0,%1,%2,%3}, {%4,%5,%6,%7}, {%8,%9}, {%0,%1,%2,%3};"
      : "+f"(c[0]), "+f"(c[1]), "+f"(c[2]), "+f"(c[3])
      : "r"(a[0]), "r"(a[1]), "r"(a[2]), "r"(a[3]), "r"(b[0]), "r"(b[1]));
}
__device__ __forceinline__ uint32_t pack_bf2(float v) {
  __nv_bfloat16 h = __float2bfloat16_rn(v);
  float fh = __bfloat162float(h);
  __nv_bfloat16 l = __float2bfloat16_rn(v - fh);
  return (uint32_t)__bfloat16_as_ushort(h) |
         ((uint32_t)__bfloat16_as_ushort(l) << 16);
}
__device__ __forceinline__ uint32_t tf32_rn(float f) {
  return __float_as_uint(f) + 0x1000u;
}

// ---------------------------------------------------------------------------
// GEMM core (unchanged from R4)
// ---------------------------------------------------------------------------
struct Term { const float* A; const float* W; const float* bias; };
struct Op   { Term t[3]; float* C; int nt; int K; int lda; int ldb; int ldc; };
struct OpTable { Op op[9]; };

template <int BN, bool PRECISE, bool PACKOUT>
__device__ __forceinline__ void gemm_core(const Op& op) {
  constexpr int BK = 16;
  constexpr int PITCH = 20;
  constexpr int WN = BN / 2;
  constexpr int NT = WN / 8;
  __shared__ uint32_t As[2][128 * PITCH];
  __shared__ uint32_t Bs[2][BN * PITCH];

  const int t = threadIdx.x;
  const int wid = t >> 5, lane = t & 31;
  const int warp_m = wid & 3;
  const int wn = wid >> 2;
  const int gid = lane >> 2, qid = lane & 3;

  const int bm = blockIdx.y * 128;
  const int bn = blockIdx.x * BN;
  const int cpt = op.K / BK;
  const int total = op.nt * cpt;

  float acc[2][NT][4];
#pragma unroll
  for (int mt = 0; mt < 2; mt++)
#pragma unroll
    for (int nt = 0; nt < NT; nt++)
#pragma unroll
      for (int j = 0; j < 4; j++) acc[mt][nt][j] = 0.f;

  auto load_chunk = [&](int c, int buf) {
    const int term = c / cpt;
    const int k0 = (c - term * cpt) * BK;
    const float* __restrict__ A = op.t[term].A;
    const float* __restrict__ W = op.t[term].W;
#pragma unroll
    for (int i = 0; i < 2; i++) {
      int f = t + i * 256;
      int r = f >> 2, c4 = (f & 3) * 4;
      cp16(&As[buf][r * PITCH + c4], A + (size_t)(bm + r) * op.lda + k0 + c4);
    }
#pragma unroll
    for (int i = 0; i < BN / 64; i++) {
      int f = t + i * 256;
      int r = f >> 2, c4 = (f & 3) * 4;
      cp16(&Bs[buf][r * PITCH + c4], W + (size_t)(bn + r) * op.ldb + k0 + c4);
    }
  };

  load_chunk(0, 0);
  cp_commit();

  for (int c = 0; c < total; c++) {
    const int buf = c & 1;
    if (c + 1 < total) load_chunk(c + 1, (c + 1) & 1);
    cp_commit();
    cp_wait<1>();
    __syncthreads();

#pragma unroll
    for (int kk = 0; kk < BK; kk += 8) {
      uint32_t af[2][4];
#pragma unroll
      for (int mt = 0; mt < 2; mt++) {
        int r0 = warp_m * 32 + mt * 16 + gid;
        uint32_t w0 = As[buf][(r0)     * PITCH + kk + qid];
        uint32_t w1 = As[buf][(r0 + 8) * PITCH + kk + qid];
        uint32_t w2 = As[buf][(r0)     * PITCH + kk + qid + 4];
        uint32_t w3 = As[buf][(r0 + 8) * PITCH + kk + qid + 4];
        if (PRECISE) {
          af[mt][0] = w0; af[mt][1] = w1; af[mt][2] = w2; af[mt][3] = w3;
        } else {
          af[mt][0] = w0 + 0x1000u; af[mt][1] = w1 + 0x1000u;
          af[mt][2] = w2 + 0x1000u; af[mt][3] = w3 + 0x1000u;
        }
      }
#pragma unroll
      for (int nt = 0; nt < NT; nt++) {
        int n0 = wn * WN + nt * 8 + gid;
        uint32_t u0 = Bs[buf][n0 * PITCH + kk + qid];
        uint32_t u1 = Bs[buf][n0 * PITCH + kk + qid + 4];
        if (PRECISE) {
          uint32_t bh[2] = {__byte_perm(u0, 0, 0x1010),
                            __byte_perm(u1, 0, 0x1010)};
          uint32_t bl[2] = {__byte_perm(u0, 0, 0x3232),
                            __byte_perm(u1, 0, 0x3232)};
#pragma unroll
          for (int mt = 0; mt < 2; mt++) {
            mma_bf16_k16(acc[mt][nt], af[mt], bh);
            mma_bf16_k16(acc[mt][nt], af[mt], bl);
          }
        } else {
          uint32_t br[2] = {u0 + 0x1000u, u1 + 0x1000u};
#pragma unroll
          for (int mt = 0; mt < 2; mt++) mma_tf32_k8(acc[mt][nt], af[mt], br);
        }
      }
    }
    __syncthreads();
  }

#pragma unroll
  for (int mt = 0; mt < 2; mt++) {
    int row0 = bm + warp_m * 32 + mt * 16 + gid;
#pragma unroll
    for (int nt = 0; nt < NT; nt++) {
      int col = bn + wn * WN + nt * 8 + qid * 2;
      float b0 = 0.f, b1 = 0.f;
      if (op.t[0].bias) {
        for (int tt = 0; tt < op.nt; tt++) {
          b0 += op.t[tt].bias[col];
          b1 += op.t[tt].bias[col + 1];
        }
      }
      float v00 = acc[mt][nt][0] + b0, v01 = acc[mt][nt][1] + b1;
      float v10 = acc[mt][nt][2] + b0, v11 = acc[mt][nt][3] + b1;
      if (PACKOUT) {
        uint32_t* Cp = (uint32_t*)op.C;
        uint2 p0 = {pack_bf2(v00), pack_bf2(v01)};
        uint2 p1 = {pack_bf2(v10), pack_bf2(v11)};
        *(uint2*)(Cp + (size_t)row0 * op.ldc + col) = p0;
        *(uint2*)(Cp + (size_t)(row0 + 8) * op.ldc + col) = p1;
      } else {
        float2 p0 = {v00, v01};
        float2 p1 = {v10, v11};
        *(float2*)(op.C + (size_t)row0 * op.ldc + col) = p0;
        *(float2*)(op.C + (size_t)(row0 + 8) * op.ldc + col) = p1;
      }
    }
  }
}

__global__ void __launch_bounds__(256) proj_precise(const OpTable tab) {
  gemm_core<128, true, true>(tab.op[blockIdx.z]);
}
__global__ void __launch_bounds__(256) proj_fast(const OpTable tab) {
  gemm_core<128, false, false>(tab.op[blockIdx.z]);
}

// ---------------------------------------------------------------------------
// Fused attention: scores (raw -> d_out) + online softmax + P@V.
// Grid (8 q-blocks, 96 = 3 streams * 32 bh). 256 threads, 8 warps.
// Warp w owns rows w*16 .. w*16+15 of its 128-row Q block.
// ---------------------------------------------------------------------------
namespace {
constexpr int TP = 68;                   // tile pitch (words)
constexpr int TILE_W = 128 * TP;         // 8704 words per tile
constexpr int FUSED_SMEM = 6 * TILE_W * 4;  // 208896 bytes
}

__global__ void __launch_bounds__(256) fused_attn(
    const uint32_t* __restrict__ qb, const uint32_t* __restrict__ kb,
    const float* __restrict__ vb, const float* __restrict__ bias0,
    const float* __restrict__ bias1, const float* __restrict__ bias2,
    float* __restrict__ score_out, float* __restrict__ ob) {
  extern __shared__ uint32_t sm[];
  uint32_t* Qs = sm;                       // [128][TP] packed
  uint32_t* Ks = sm + TILE_W;              // [2][128][TP] packed
  float*    Vs = (float*)(sm + 3 * TILE_W);// [2][128][TP] fp32
  float*    Ps = (float*)(sm + 5 * TILE_W);// [128][TP] fp32 (half P tile)

  const int zz = blockIdx.y;
  const int st = zz >> 5, bh = zz & 31, b = bh >> 4, h = bh & 15;
  const int q0 = blockIdx.x * 128;

  const uint32_t* qp = qb + (size_t)st * NTOK + (size_t)(b * S_ + q0) * DH_ + h * HD_;
  const uint32_t* kp = kb + (size_t)st * NTOK + (size_t)b * S_ * DH_ + h * HD_;
  const float*    vp = vb + (size_t)st * NTOK + (size_t)b * S_ * DH_ + h * HD_;
  const float* bias = (st == 0) ? bias0 : (st == 1) ? bias1 : bias2;
  const float* brow = bias + (size_t)bh * S_ * S_ + (size_t)q0 * S_;
  float* srow = score_out + (size_t)st * NSC + (size_t)bh * S_ * S_ + (size_t)q0 * S_;
  float* op = ob + (size_t)st * NTOK + (size_t)(b * S_ + q0) * DH_ + h * HD_;

  const int t = threadIdx.x;
  const int w = t >> 5, lane = t & 31;
  const int gid = lane >> 2, qid = lane & 3;
  const int r0 = w * 16 + gid;             // row within q block (and r0+8)

  // ---- loads ----
  auto load_q = [&]() {
#pragma unroll
    for (int i = 0; i < 8; i++) {
      int f = t + i * 256;
      int r = f >> 4, c4 = (f & 15) * 4;
      cp16(&Qs[r * TP + c4], qp + (size_t)r * DH_ + c4);
    }
  };
  auto load_kv = [&](int kbk, int buf) {
#pragma unroll
    for (int i = 0; i < 8; i++) {
      int f = t + i * 256;
      int r = f >> 4, c4 = (f & 15) * 4;
      cp16(&Ks[buf * TILE_W + r * TP + c4],
           kp + (size_t)(kbk * 128 + r) * DH_ + c4);
      cp16(&Vs[buf * TILE_W + r * TP + c4],
           vp + (size_t)(kbk * 128 + r) * DH_ + c4);
    }
  };

  load_q();
  load_kv(0, 0);
  cp_commit();
  load_kv(1, 1);
  cp_commit();

  // ---- online softmax state ----
  float m0 = -1e30f, m1 = -1e30f, l0 = 0.f, l1 = 0.f;
  float oacc[8][4];
#pragma unroll
  for (int j = 0; j < 8; j++)
#pragma unroll
    for (int q = 0; q < 4; q++) oacc[j][q] = 0.f;

  for (int it = 0; it < 8; it++) {
    const int buf = it & 1;
    cp_wait<1>();
    __syncthreads();

    // ---- scores: acc[16][4] = Q(16 rows) x K(128 cols), packed bf16 2-MMA
    float acc[16][4];
#pragma unroll
    for (int nt = 0; nt < 16; nt++)
#pragma unroll
      for (int q = 0; q < 4; q++) acc[nt][q] = 0.f;

#pragma unroll
    for (int kk = 0; kk < 64; kk += 8) {
      uint32_t af[4];
      af[0] = Qs[(r0)     * TP + kk + qid];
      af[1] = Qs[(r0 + 8) * TP + kk + qid];
      af[2] = Qs[(r0)     * TP + kk + qid + 4];
      af[3] = Qs[(r0 + 8) * TP + kk + qid + 4];
#pragma unroll
      for (int nt = 0; nt < 16; nt++) {
        int n0 = nt * 8 + gid;
        uint32_t u0 = Ks[buf * TILE_W + n0 * TP + kk + qid];
        uint32_t u1 = Ks[buf * TILE_W + n0 * TP + kk + qid + 4];
        uint32_t bh2[2] = {__byte_perm(u0, 0, 0x1010), __byte_perm(u1, 0, 0x1010)};
        uint32_t bl2[2] = {__byte_perm(u0, 0, 0x3232), __byte_perm(u1, 0, 0x3232)};
        mma_bf16_k16(acc[nt], af, bh2);
        mma_bf16_k16(acc[nt], af, bl2);
      }
    }

    // ---- write RAW scores, then add bias ----
    const int cbase = it * 128;
#pragma unroll
    for (int nt = 0; nt < 16; nt++) {
      int col = cbase + nt * 8 + qid * 2;
      *(float2*)(srow + (size_t)(r0)     * S_ + col) = {acc[nt][0], acc[nt][1]};
      *(float2*)(srow + (size_t)(r0 + 8) * S_ + col) = {acc[nt][2], acc[nt][3]};
      float2 bv0 = *(const float2*)(brow + (size_t)(r0)     * S_ + col);
      float2 bv1 = *(const float2*)(brow + (size_t)(r0 + 8) * S_ + col);
      acc[nt][0] += bv0.x; acc[nt][1] += bv0.y;
      acc[nt][2] += bv1.x; acc[nt][3] += bv1.y;
    }

    // ---- row max (rows r0, r0+8) ----
    float mt0 = -1e30f, mt1 = -1e30f;
#pragma unroll
    for (int nt = 0; nt < 16; nt++) {
      mt0 = fmaxf(mt0, fmaxf(acc[nt][0], acc[nt][1]));
      mt1 = fmaxf(mt1, fmaxf(acc[nt][2], acc[nt][3]));
    }
    mt0 = fmaxf(mt0, __shfl_xor_sync(0xffffffffu, mt0, 1));
    mt0 = fmaxf(mt0, __shfl_xor_sync(0xffffffffu, mt0, 2));
    mt1 = fmaxf(mt1, __shfl_xor_sync(0xffffffffu, mt1, 1));
    mt1 = fmaxf(mt1, __shfl_xor_sync(0xffffffffu, mt1, 2));

    float m0n = fmaxf(m0, mt0), m1n = fmaxf(m1, mt1);
    float sc0 = __expf(m0 - m0n), sc1 = __expf(m1 - m1n);
    m0 = m0n; m1 = m1n;
    l0 *= sc0; l1 *= sc1;
#pragma unroll
    for (int j = 0; j < 8; j++) {
      oacc[j][0] *= sc0; oacc[j][1] *= sc0;
      oacc[j][2] *= sc1; oacc[j][3] *= sc1;
    }

    // ---- two half-tiles: exp -> Ps, then PV ----
#pragma unroll
    for (int hh = 0; hh < 2; hh++) {
      float ts0 = 0.f, ts1 = 0.f;
#pragma unroll
      for (int j = 0; j < 8; j++) {
        int nt = hh * 8 + j;
        float p00 = __expf(acc[nt][0] - m0);
        float p01 = __expf(acc[nt][1] - m0);
        float p10 = __expf(acc[nt][2] - m1);
        float p11 = __expf(acc[nt][3] - m1);
        ts0 += p00 + p01; ts1 += p10 + p11;
        int pc = j * 8 + qid * 2;
        *(float2*)(&Ps[(r0)     * TP + pc]) = {p00, p01};
        *(float2*)(&Ps[(r0 + 8) * TP + pc]) = {p10, p11};
      }
      ts0 += __shfl_xor_sync(0xffffffffu, ts0, 1);
      ts0 += __shfl_xor_sync(0xffffffffu, ts0, 2);
      ts1 += __shfl_xor_sync(0xffffffffu, ts1, 1);
      ts1 += __shfl_xor_sync(0xffffffffu, ts1, 2);
      l0 += ts0; l1 += ts1;
      __syncthreads();

      // PV: oacc[16 rows][64 cols] += P[16][64] @ V[64(+off)][64]
#pragma unroll
      for (int kkl = 0; kkl < 64; kkl += 8) {
        uint32_t ap[4];
        ap[0] = tf32_rn(Ps[(r0)     * TP + kkl + qid]);
        ap[1] = tf32_rn(Ps[(r0 + 8) * TP + kkl + qid]);
        ap[2] = tf32_rn(Ps[(r0)     * TP + kkl + qid + 4]);
        ap[3] = tf32_rn(Ps[(r0 + 8) * TP + kkl + qid + 4]);
        int kv = hh * 64 + kkl;
#pragma unroll
        for (int j = 0; j < 8; j++) {
          int n0 = j * 8 + gid;
          uint32_t bv[2];
          bv[0] = tf32_rn(Vs[buf * TILE_W + (kv + qid) * TP + n0]);
          bv[1] = tf32_rn(Vs[buf * TILE_W + (kv + qid + 4) * TP + n0]);
          mma_tf32_k8(oacc[j], ap, bv);
        }
      }
      __syncthreads();
    }

    // prefetch tile it+2 into this buffer (now free)
    if (it + 2 < 8) load_kv(it + 2, buf);
    cp_commit();
  }

  // ---- finalize: o = oacc / l ----
  float inv0 = 1.f / l0, inv1 = 1.f / l1;
#pragma unroll
  for (int j = 0; j < 8; j++) {
    int col = j * 8 + qid * 2;
    *(float2*)(op + (size_t)(r0)     * DH_ + col) =
        {oacc[j][0] * inv0, oacc[j][1] * inv0};
    *(float2*)(op + (size_t)(r0 + 8) * DH_ + col) =
        {oacc[j][2] * inv1, oacc[j][3] * inv1};
  }
}

// ---- input packing ----
__global__ void __launch_bounds__(256) pack_inputs(const float* __restrict__ src,
                                                   uint32_t* __restrict__ dst,
                                                   int n) {
  int i = blockIdx.x * 256 + threadIdx.x;
  if (i < n) dst[i] = pack_bf2(src[i]);
}

// ---- weight transpose ----
struct WEnt { const float* src; float* dst; int K; int pack; };
struct WTab { WEnt e[12]; };

__global__ void __launch_bounds__(256) transpose_w(const WTab tab) {
  WEnt e = tab.e[blockIdx.z];
  int n0 = blockIdx.x * 32, k0 = blockIdx.y * 32;
  if (k0 >= e.K) return;
  __shared__ float tl[32][33];
  int tx = threadIdx.x, ty = threadIdx.y;
#pragma unroll
  for (int i = 0; i < 32; i += 8)
    tl[ty + i][tx] = e.src[(size_t)(k0 + ty + i) * DH_ + n0 + tx];
  __syncthreads();
#pragma unroll
  for (int i = 0; i < 32; i += 8) {
    float v = tl[tx][ty + i];
    if (e.pack) v = __uint_as_float(pack_bf2(v));
    e.dst[(size_t)(n0 + ty + i) * e.K + k0 + tx] = v;
  }
}

// ---- residual chain ----
__global__ void __launch_bounds__(256) combine_kernel(
    const float* __restrict__ s, const float* __restrict__ b,
    const float* __restrict__ z, const float* __restrict__ ps,
    const float* __restrict__ pb, const float* __restrict__ pz,
    float* __restrict__ os, float* __restrict__ ob, float* __restrict__ oz) {
  size_t i = (size_t)blockIdx.x * 256 + threadIdx.x;
  if (i >= NTOK) return;
  float so = s[i] + ps[i];
  float bo = so + b[i] + pb[i];
  float zo = bo + z[i] + pz[i];
  os[i] = so; ob[i] = bo; oz[i] = zo;
}

// ===========================================================================
extern "C" void kernel_launch(void* const* d_in, const int* in_sizes, int n_in,
                              void* d_out, int out_size) {
  const float* y    = (const float*)d_in[0];
  const float* s    = (const float*)d_in[1];
  const float* b    = (const float*)d_in[2];
  const float* z    = (const float*)d_in[3];
  const float* ba0  = (const float*)d_in[4];
  const float* ba1  = (const float*)d_in[5];
  const float* ba2  = (const float*)d_in[6];
  const float* W[12] = {
      (const float*)d_in[7],  (const float*)d_in[9],  (const float*)d_in[11],
      (const float*)d_in[13], (const float*)d_in[15], (const float*)d_in[17],
      (const float*)d_in[19], (const float*)d_in[21],
      (const float*)d_in[23], (const float*)d_in[25], (const float*)d_in[27],
      (const float*)d_in[29]};
  const float* C[12] = {
      (const float*)d_in[8],  (const float*)d_in[10], (const float*)d_in[12],
      (const float*)d_in[14], (const float*)d_in[16], (const float*)d_in[18],
      (const float*)d_in[20], (const float*)d_in[22],
      (const float*)d_in[24], (const float*)d_in[26], (const float*)d_in[28],
      (const float*)d_in[30]};
  const int KW[12] = {DIN_, DIN_, DIN_, DH_, DH_, DH_, DH_, DH_,
                      DH_, DH_, DH_, DH_};

  float* out   = (float*)d_out;
  float* s_out = out;
  float* b_out = out + NTOK;
  float* z_out = out + 2 * NTOK;
  float* scb   = out + 3 * NTOK;

  uint32_t *gq, *gk, *gyp, *gsp, *gbp, *gzp;
  float *gv, *go, *gp, *gwt;
  cudaGetSymbolAddress((void**)&gq, g_q);
  cudaGetSymbolAddress((void**)&gk, g_k);
  cudaGetSymbolAddress((void**)&gv, g_v);
  cudaGetSymbolAddress((void**)&go, g_o);
  cudaGetSymbolAddress((void**)&gp, g_p);
  cudaGetSymbolAddress((void**)&gwt, g_wt);
  cudaGetSymbolAddress((void**)&gyp, g_ypk);
  cudaGetSymbolAddress((void**)&gsp, g_spk);
  cudaGetSymbolAddress((void**)&gbp, g_bpk);
  cudaGetSymbolAddress((void**)&gzp, g_zpk);

  cudaFuncSetAttribute(fused_attn, cudaFuncAttributeMaxDynamicSharedMemorySize,
                       FUSED_SMEM);

  // --- 1a: pack inputs to bf16x2 ---
  pack_inputs<<<(M_ * DIN_ + 255) / 256, 256>>>(y, gyp, M_ * DIN_);
  pack_inputs<<<(M_ * DH_ + 255) / 256, 256>>>(s, gsp, M_ * DH_);
  pack_inputs<<<(M_ * DH_ + 255) / 256, 256>>>(b, gbp, M_ * DH_);
  pack_inputs<<<(M_ * DH_ + 255) / 256, 256>>>(z, gzp, M_ * DH_);

  // --- 1b: transpose weights (pack precise ones: indices 0..7) ---
  WTab wt{};
  for (int i = 0; i < 12; i++)
    wt.e[i] = {W[i], gwt + (size_t)i * DH_ * DH_, KW[i], i < 8 ? 1 : 0};
  transpose_w<<<dim3(32, 32, 12), dim3(32, 8)>>>(wt);

  auto WT = [&](int i) -> const float* { return gwt + (size_t)i * DH_ * DH_; };

  auto setop = [&](OpTable& tb, int idx, float* Cp, int K, int nt,
                   const float* A0, int w0,
                   const float* A1 = nullptr, int w1 = -1,
                   const float* A2 = nullptr, int w2 = -1) {
    Op& o = tb.op[idx];
    o.C = Cp; o.K = K; o.nt = nt; o.lda = K; o.ldb = K; o.ldc = DH_;
    o.t[0] = {A0, WT(w0), C[w0]};
    if (nt > 1) o.t[1] = {A1, WT(w1), C[w1]};
    if (nt > 2) o.t[2] = {A2, WT(w2), C[w2]};
  };

  const float* yp = (const float*)gyp;
  const float* sp = (const float*)gsp;
  const float* bp = (const float*)gbp;
  const float* zp = (const float*)gzp;

  // --- 2a: Q + K projections (precise, packed output) ---
  OpTable tqk{};
  setop(tqk, 0, (float*)(gq + 0 * NTOK), DIN_, 1, yp, 0);
  setop(tqk, 1, (float*)(gq + 1 * NTOK), DIN_, 1, yp, 1);
  setop(tqk, 2, (float*)(gq + 2 * NTOK), DIN_, 1, yp, 2);
  setop(tqk, 3, (float*)(gk + 0 * NTOK), DH_, 2, sp, 3, bp, 4);
  setop(tqk, 4, (float*)(gk + 1 * NTOK), DH_, 3, bp, 6, sp, 4, zp, 5);
  setop(tqk, 5, (float*)(gk + 2 * NTOK), DH_, 2, zp, 7, bp, 5);
  proj_precise<<<dim3(8, 16, 6), 256>>>(tqk);

  // --- 2b: V projections (fast tf32) ---
  OpTable tv{};
  setop(tv, 0, gv + 0 * NTOK, DH_, 1, s, 8);
  setop(tv, 1, gv + 1 * NTOK, DH_, 1, b, 9);
  setop(tv, 2, gv + 2 * NTOK, DH_, 1, z, 10);
  proj_fast<<<dim3(8, 16, 3), 256>>>(tv);

  // --- 3: fused attention (scores raw -> d_out, softmax, PV) ---
  fused_attn<<<dim3(8, 96), 256, FUSED_SMEM>>>(gq, gk, gv, ba0, ba1, ba2,
                                               scb, go);

  // --- 4: output projections (fast tf32) ---
  OpTable to{};
  for (int i = 0; i < 3; i++)
    setop(to, i, gp + (size_t)i * NTOK, DH_, 1, go + (size_t)i * NTOK, 11);
  proj_fast<<<dim3(8, 16, 3), 256>>>(to);

  // --- 5: residual chain ---
  combine_kernel<<<(int)((NTOK + 255) / 256), 256>>>(
      s, b, z, gp + 0 * NTOK, gp + 1 * NTOK, gp + 2 * NTOK,
      s_out, b_out, z_out);
}

// round 7
// speedup vs baseline: 3.8616x; 1.2028x over previous
#include <cuda_runtime.h>
#include <cuda_bf16.h>
#include <cuda_fp16.h>
#include <cstdint>
#include <math.h>

// ===========================================================================
// MarkovBlanketAttention on sm_103 — R6:
// Precise chain (Q/K proj, QK^T): packed-bf16x2 2-MMA (unchanged).
// Fast chain (V proj, PV, out proj): packed-f16-pair single m16n8k16 MMA
// (same unit roundoff as tf32, half the instructions and operand traffic).
// ===========================================================================

namespace {
constexpr int B_   = 2;
constexpr int S_   = 1024;
constexpr int DIN_ = 512;
constexpr int DH_  = 1024;
constexpr int H_   = 16;
constexpr int HD_  = 64;
constexpr int M_   = B_ * S_;
constexpr size_t NTOK = (size_t)M_ * DH_;
constexpr size_t NSC  = (size_t)B_ * H_ * S_ * S_;
}

// ---- scratch (device globals) ----
__device__ uint32_t g_q[3][NTOK];          // packed bf16x2 Q
__device__ uint32_t g_k[3][NTOK];          // packed bf16x2 K
__device__ float    g_v[3][NTOK];          // fp32 V
__device__ uint32_t g_of[3][NTOK / 2];     // attention out, packed f16 pairs
__device__ float    g_p[3][NTOK];
__device__ float    g_wt[8][DH_ * DH_];    // precise W^T (bf2-packed bits)
__device__ uint32_t g_wtf[4][DH_ * DH_ / 2]; // fast W^T, f16 pairs [n][K/2]
__device__ uint32_t g_vth[96][HD_ * S_ / 2]; // V^T f16 pairs [col][S/2]
__device__ uint32_t g_ypk[M_ * DIN_];      // bf2-packed inputs
__device__ uint32_t g_spk[M_ * DH_];
__device__ uint32_t g_bpk[M_ * DH_];
__device__ uint32_t g_zpk[M_ * DH_];
__device__ uint32_t g_sfh[M_ * DH_ / 2];   // f16-pair-packed inputs
__device__ uint32_t g_bfh[M_ * DH_ / 2];
__device__ uint32_t g_zfh[M_ * DH_ / 2];

// ---------------------------------------------------------------------------
// helpers
// ---------------------------------------------------------------------------
__device__ __forceinline__ uint32_t smem_u32(const void* p) {
  uint32_t a;
  asm("{ .reg .u64 t; cvta.to.shared.u64 t, %1; cvt.u32.u64 %0, t; }"
      : "=r"(a) : "l"(p));
  return a;
}
__device__ __forceinline__ void cp16(void* smem, const void* g) {
  asm volatile("cp.async.cg.shared.global [%0], [%1], 16;"
               :: "r"(smem_u32(smem)), "l"(g));
}
__device__ __forceinline__ void cp_commit() {
  asm volatile("cp.async.commit_group;" ::: "memory");
}
template <int N>
__device__ __forceinline__ void cp_wait() {
  asm volatile("cp.async.wait_group %0;" :: "n"(N) : "memory");
}
__device__ __forceinline__ void mma_bf16_k16(float* c, const uint32_t* a,
                                             const uint32_t* b) {
  asm volatile(
      "mma.sync.aligned.m16n8k16.row.col.f32.bf16.bf16.f32 "
      "{%0,%1,%2,%3}, {%4,%5,%6,%7}, {%8,%9}, {%0,%1,%2,%3};"
      : "+f"(c[0]), "+f"(c[1]), "+f"(c[2]), "+f"(c[3])
      : "r"(a[0]), "r"(a[1]), "r"(a[2]), "r"(a[3]), "r"(b[0]), "r"(b[1]));
}
__device__ __forceinline__ void mma_f16_k16(float* c, const uint32_t* a,
                                            const uint32_t* b) {
  asm volatile(
      "mma.sync.aligned.m16n8k16.row.col.f32.f16.f16.f32 "
      "{%0,%1,%2,%3}, {%4,%5,%6,%7}, {%8,%9}, {%0,%1,%2,%3};"
      : "+f"(c[0]), "+f"(c[1]), "+f"(c[2]), "+f"(c[3])
      : "r"(a[0]), "r"(a[1]), "r"(a[2]), "r"(a[3]), "r"(b[0]), "r"(b[1]));
}
__device__ __forceinline__ uint32_t pack_bf2(float v) {
  __nv_bfloat16 h = __float2bfloat16_rn(v);
  float fh = __bfloat162float(h);
  __nv_bfloat16 l = __float2bfloat16_rn(v - fh);
  return (uint32_t)__bfloat16_as_ushort(h) |
         ((uint32_t)__bfloat16_as_ushort(l) << 16);
}
__device__ __forceinline__ uint32_t pack_f16p(float a, float b) {
  __half2 h = __floats2half2_rn(a, b);   // .x (low bits) = a = even k
  return *(uint32_t*)&h;
}

// ---------------------------------------------------------------------------
// GEMM core.  MODE 0 = fast f16-pair (1 MMA / 16 true-k, word = 2 k)
//             MODE 1 = precise bf16x2 (2 MMA / 16 true-k, word = 1 k)
// op.K, lda, ldb are in WORDS.
// ---------------------------------------------------------------------------
struct Term { const uint32_t* A; const uint32_t* W; const float* bias; };
struct Op   { Term t[3]; float* C; int nt; int K; int lda; int ldb; int ldc; };
struct OpTable { Op op[9]; };

template <int BN, int MODE, bool PACKOUT>
__device__ __forceinline__ void gemm_core(const Op& op) {
  constexpr int BK = 16;
  constexpr int PITCH = 20;
  constexpr int WN = BN / 2;
  constexpr int NT = WN / 8;
  __shared__ uint32_t As[2][128 * PITCH];
  __shared__ uint32_t Bs[2][BN * PITCH];

  const int t = threadIdx.x;
  const int wid = t >> 5, lane = t & 31;
  const int warp_m = wid & 3;
  const int wn = wid >> 2;
  const int gid = lane >> 2, qid = lane & 3;

  const int bm = blockIdx.y * 128;
  const int bn = blockIdx.x * BN;
  const int cpt = op.K / BK;
  const int total = op.nt * cpt;

  float acc[2][NT][4];
#pragma unroll
  for (int mt = 0; mt < 2; mt++)
#pragma unroll
    for (int nt = 0; nt < NT; nt++)
#pragma unroll
      for (int j = 0; j < 4; j++) acc[mt][nt][j] = 0.f;

  auto load_chunk = [&](int c, int buf) {
    const int term = c / cpt;
    const int k0 = (c - term * cpt) * BK;
    const uint32_t* __restrict__ A = op.t[term].A;
    const uint32_t* __restrict__ W = op.t[term].W;
#pragma unroll
    for (int i = 0; i < 2; i++) {
      int f = t + i * 256;
      int r = f >> 2, c4 = (f & 3) * 4;
      cp16(&As[buf][r * PITCH + c4], A + (size_t)(bm + r) * op.lda + k0 + c4);
    }
#pragma unroll
    for (int i = 0; i < BN / 64; i++) {
      int f = t + i * 256;
      int r = f >> 2, c4 = (f & 3) * 4;
      cp16(&Bs[buf][r * PITCH + c4], W + (size_t)(bn + r) * op.ldb + k0 + c4);
    }
  };

  load_chunk(0, 0);
  cp_commit();

  for (int c = 0; c < total; c++) {
    const int buf = c & 1;
    if (c + 1 < total) load_chunk(c + 1, (c + 1) & 1);
    cp_commit();
    cp_wait<1>();
    __syncthreads();

#pragma unroll
    for (int kk = 0; kk < BK; kk += 8) {
      uint32_t af[2][4];
#pragma unroll
      for (int mt = 0; mt < 2; mt++) {
        int r0 = warp_m * 32 + mt * 16 + gid;
        af[mt][0] = As[buf][(r0)     * PITCH + kk + qid];
        af[mt][1] = As[buf][(r0 + 8) * PITCH + kk + qid];
        af[mt][2] = As[buf][(r0)     * PITCH + kk + qid + 4];
        af[mt][3] = As[buf][(r0 + 8) * PITCH + kk + qid + 4];
      }
#pragma unroll
      for (int nt = 0; nt < NT; nt++) {
        int n0 = wn * WN + nt * 8 + gid;
        uint32_t u0 = Bs[buf][n0 * PITCH + kk + qid];
        uint32_t u1 = Bs[buf][n0 * PITCH + kk + qid + 4];
        if (MODE == 1) {
          uint32_t bh[2] = {__byte_perm(u0, 0, 0x1010),
                            __byte_perm(u1, 0, 0x1010)};
          uint32_t bl[2] = {__byte_perm(u0, 0, 0x3232),
                            __byte_perm(u1, 0, 0x3232)};
#pragma unroll
          for (int mt = 0; mt < 2; mt++) {
            mma_bf16_k16(acc[mt][nt], af[mt], bh);
            mma_bf16_k16(acc[mt][nt], af[mt], bl);
          }
        } else {
          uint32_t br[2] = {u0, u1};
#pragma unroll
          for (int mt = 0; mt < 2; mt++) mma_f16_k16(acc[mt][nt], af[mt], br);
        }
      }
    }
    __syncthreads();
  }

#pragma unroll
  for (int mt = 0; mt < 2; mt++) {
    int row0 = bm + warp_m * 32 + mt * 16 + gid;
#pragma unroll
    for (int nt = 0; nt < NT; nt++) {
      int col = bn + wn * WN + nt * 8 + qid * 2;
      float b0 = 0.f, b1 = 0.f;
      if (op.t[0].bias) {
        for (int tt = 0; tt < op.nt; tt++) {
          b0 += op.t[tt].bias[col];
          b1 += op.t[tt].bias[col + 1];
        }
      }
      float v00 = acc[mt][nt][0] + b0, v01 = acc[mt][nt][1] + b1;
      float v10 = acc[mt][nt][2] + b0, v11 = acc[mt][nt][3] + b1;
      if (PACKOUT) {
        uint32_t* Cp = (uint32_t*)op.C;
        uint2 p0 = {pack_bf2(v00), pack_bf2(v01)};
        uint2 p1 = {pack_bf2(v10), pack_bf2(v11)};
        *(uint2*)(Cp + (size_t)row0 * op.ldc + col) = p0;
        *(uint2*)(Cp + (size_t)(row0 + 8) * op.ldc + col) = p1;
      } else {
        *(float2*)(op.C + (size_t)row0 * op.ldc + col) = {v00, v01};
        *(float2*)(op.C + (size_t)(row0 + 8) * op.ldc + col) = {v10, v11};
      }
    }
  }
}

__global__ void __launch_bounds__(256) proj_precise(const OpTable tab) {
  gemm_core<128, 1, true>(tab.op[blockIdx.z]);
}
__global__ void __launch_bounds__(256) proj_f16(const OpTable tab) {
  gemm_core<128, 0, false>(tab.op[blockIdx.z]);
}

// ---------------------------------------------------------------------------
// Fused attention: scores (raw -> d_out) + online softmax + P@V (f16).
// Grid (8 q-blocks, 96). 256 threads, 8 warps; warp owns 16 q-rows.
// ---------------------------------------------------------------------------
namespace {
constexpr int TP = 68;                       // pitch (words)
constexpr int QK_W = 128 * TP;               // Q / K / P tiles
constexpr int VT_W = 64 * TP;                // V^T tile (64 cols x 64 words)
constexpr int FUSED_SMEM = (3 * QK_W + 2 * VT_W + QK_W) * 4;  // 174080 B
}

__global__ void __launch_bounds__(256) fused_attn(
    const uint32_t* __restrict__ qb, const uint32_t* __restrict__ kb,
    const uint32_t* __restrict__ vtb, const float* __restrict__ bias0,
    const float* __restrict__ bias1, const float* __restrict__ bias2,
    float* __restrict__ score_out, uint32_t* __restrict__ ofb) {
  extern __shared__ uint32_t sm[];
  uint32_t* Qs = sm;                         // [128][TP] bf2
  uint32_t* Ks = sm + QK_W;                  // [2][128][TP] bf2
  uint32_t* VT = sm + 3 * QK_W;              // [2][64][TP] f16 pairs
  uint32_t* Ps = sm + 3 * QK_W + 2 * VT_W;   // [128][TP] f16 pairs

  const int zz = blockIdx.y;
  const int st = zz >> 5, bh = zz & 31, b = bh >> 4, h = bh & 15;
  const int q0 = blockIdx.x * 128;

  const uint32_t* qp = qb + (size_t)st * NTOK + (size_t)(b * S_ + q0) * DH_ + h * HD_;
  const uint32_t* kp = kb + (size_t)st * NTOK + (size_t)b * S_ * DH_ + h * HD_;
  const uint32_t* vtp = vtb + (size_t)zz * (HD_ * S_ / 2);
  const float* bias = (st == 0) ? bias0 : (st == 1) ? bias1 : bias2;
  const float* brow = bias + (size_t)bh * S_ * S_ + (size_t)q0 * S_;
  float* srow = score_out + (size_t)st * NSC + (size_t)bh * S_ * S_ + (size_t)q0 * S_;
  uint32_t* ofp = ofb + (size_t)st * (NTOK / 2) + (size_t)(b * S_ + q0) * (DH_ / 2) + h * (HD_ / 2);

  const int t = threadIdx.x;
  const int w = t >> 5, lane = t & 31;
  const int gid = lane >> 2, qid = lane & 3;
  const int r0 = w * 16 + gid;

  auto load_q = [&]() {
#pragma unroll
    for (int i = 0; i < 8; i++) {
      int f = t + i * 256;
      int r = f >> 4, c4 = (f & 15) * 4;
      cp16(&Qs[r * TP + c4], qp + (size_t)r * DH_ + c4);
    }
  };
  auto load_kv = [&](int kbk, int buf) {
#pragma unroll
    for (int i = 0; i < 8; i++) {          // K tile: 128 x 64 words
      int f = t + i * 256;
      int r = f >> 4, c4 = (f & 15) * 4;
      cp16(&Ks[buf * QK_W + r * TP + c4],
           kp + (size_t)(kbk * 128 + r) * DH_ + c4);
    }
#pragma unroll
    for (int i = 0; i < 4; i++) {          // VT tile: 64 cols x 64 words
      int f = t + i * 256;
      int r = f >> 4, c4 = (f & 15) * 4;
      cp16(&VT[buf * VT_W + r * TP + c4],
           vtp + (size_t)r * (S_ / 2) + kbk * 64 + c4);
    }
  };

  load_q();
  load_kv(0, 0);
  cp_commit();
  load_kv(1, 1);
  cp_commit();

  float m0 = -1e30f, m1 = -1e30f, l0 = 0.f, l1 = 0.f;
  float oacc[8][4];
#pragma unroll
  for (int j = 0; j < 8; j++)
#pragma unroll
    for (int q = 0; q < 4; q++) oacc[j][q] = 0.f;

  for (int it = 0; it < 8; it++) {
    const int buf = it & 1;
    cp_wait<1>();
    __syncthreads();

    // ---- scores: precise bf16x2 2-MMA
    float acc[16][4];
#pragma unroll
    for (int nt = 0; nt < 16; nt++)
#pragma unroll
      for (int q = 0; q < 4; q++) acc[nt][q] = 0.f;

#pragma unroll
    for (int kk = 0; kk < 64; kk += 8) {
      uint32_t af[4];
      af[0] = Qs[(r0)     * TP + kk + qid];
      af[1] = Qs[(r0 + 8) * TP + kk + qid];
      af[2] = Qs[(r0)     * TP + kk + qid + 4];
      af[3] = Qs[(r0 + 8) * TP + kk + qid + 4];
#pragma unroll
      for (int nt = 0; nt < 16; nt++) {
        int n0 = nt * 8 + gid;
        uint32_t u0 = Ks[buf * QK_W + n0 * TP + kk + qid];
        uint32_t u1 = Ks[buf * QK_W + n0 * TP + kk + qid + 4];
        uint32_t bh2[2] = {__byte_perm(u0, 0, 0x1010), __byte_perm(u1, 0, 0x1010)};
        uint32_t bl2[2] = {__byte_perm(u0, 0, 0x3232), __byte_perm(u1, 0, 0x3232)};
        mma_bf16_k16(acc[nt], af, bh2);
        mma_bf16_k16(acc[nt], af, bl2);
      }
    }

    // ---- raw scores out, add bias ----
    const int cbase = it * 128;
#pragma unroll
    for (int nt = 0; nt < 16; nt++) {
      int col = cbase + nt * 8 + qid * 2;
      *(float2*)(srow + (size_t)(r0)     * S_ + col) = {acc[nt][0], acc[nt][1]};
      *(float2*)(srow + (size_t)(r0 + 8) * S_ + col) = {acc[nt][2], acc[nt][3]};
      float2 bv0 = *(const float2*)(brow + (size_t)(r0)     * S_ + col);
      float2 bv1 = *(const float2*)(brow + (size_t)(r0 + 8) * S_ + col);
      acc[nt][0] += bv0.x; acc[nt][1] += bv0.y;
      acc[nt][2] += bv1.x; acc[nt][3] += bv1.y;
    }

    // ---- online softmax ----
    float mt0 = -1e30f, mt1 = -1e30f;
#pragma unroll
    for (int nt = 0; nt < 16; nt++) {
      mt0 = fmaxf(mt0, fmaxf(acc[nt][0], acc[nt][1]));
      mt1 = fmaxf(mt1, fmaxf(acc[nt][2], acc[nt][3]));
    }
    mt0 = fmaxf(mt0, __shfl_xor_sync(0xffffffffu, mt0, 1));
    mt0 = fmaxf(mt0, __shfl_xor_sync(0xffffffffu, mt0, 2));
    mt1 = fmaxf(mt1, __shfl_xor_sync(0xffffffffu, mt1, 1));
    mt1 = fmaxf(mt1, __shfl_xor_sync(0xffffffffu, mt1, 2));

    float m0n = fmaxf(m0, mt0), m1n = fmaxf(m1, mt1);
    float sc0 = __expf(m0 - m0n), sc1 = __expf(m1 - m1n);
    m0 = m0n; m1 = m1n;
    l0 *= sc0; l1 *= sc1;
#pragma unroll
    for (int j = 0; j < 8; j++) {
      oacc[j][0] *= sc0; oacc[j][1] *= sc0;
      oacc[j][2] *= sc1; oacc[j][3] *= sc1;
    }

    // ---- exp -> Ps (f16 pairs; per-warp-private rows, no sync needed) ----
    float ts0 = 0.f, ts1 = 0.f;
#pragma unroll
    for (int nt = 0; nt < 16; nt++) {
      float p00 = __expf(acc[nt][0] - m0);
      float p01 = __expf(acc[nt][1] - m0);
      float p10 = __expf(acc[nt][2] - m1);
      float p11 = __expf(acc[nt][3] - m1);
      ts0 += p00 + p01; ts1 += p10 + p11;
      Ps[(r0)     * TP + nt * 4 + qid] = pack_f16p(p00, p01);
      Ps[(r0 + 8) * TP + nt * 4 + qid] = pack_f16p(p10, p11);
    }
    ts0 += __shfl_xor_sync(0xffffffffu, ts0, 1);
    ts0 += __shfl_xor_sync(0xffffffffu, ts0, 2);
    ts1 += __shfl_xor_sync(0xffffffffu, ts1, 1);
    ts1 += __shfl_xor_sync(0xffffffffu, ts1, 2);
    l0 += ts0; l1 += ts1;

    // ---- PV: f16 k16, 8 word-chunks cover 128 tokens ----
#pragma unroll
    for (int kw = 0; kw < 64; kw += 8) {
      uint32_t ap[4];
      ap[0] = Ps[(r0)     * TP + kw + qid];
      ap[1] = Ps[(r0 + 8) * TP + kw + qid];
      ap[2] = Ps[(r0)     * TP + kw + qid + 4];
      ap[3] = Ps[(r0 + 8) * TP + kw + qid + 4];
#pragma unroll
      for (int j = 0; j < 8; j++) {
        int n0 = j * 8 + gid;
        uint32_t bv[2];
        bv[0] = VT[buf * VT_W + n0 * TP + kw + qid];
        bv[1] = VT[buf * VT_W + n0 * TP + kw + qid + 4];
        mma_f16_k16(oacc[j], ap, bv);
      }
    }
    __syncthreads();

    if (it + 2 < 8) load_kv(it + 2, buf);
    cp_commit();
  }

  // ---- finalize: o packed f16 pairs -> g_of ----
  float inv0 = 1.f / l0, inv1 = 1.f / l1;
#pragma unroll
  for (int j = 0; j < 8; j++) {
    int cw = j * 4 + qid;
    ofp[(size_t)(r0)     * (DH_ / 2) + cw] =
        pack_f16p(oacc[j][0] * inv0, oacc[j][1] * inv0);
    ofp[(size_t)(r0 + 8) * (DH_ / 2) + cw] =
        pack_f16p(oacc[j][2] * inv1, oacc[j][3] * inv1);
  }
}

// ---- fused input packing: y->bf2; s,b,z->bf2 + f16 pairs ----
__global__ void __launch_bounds__(256) pack_all(
    const float* __restrict__ y, const float* __restrict__ s,
    const float* __restrict__ b, const float* __restrict__ z,
    uint32_t* __restrict__ ypk, uint32_t* __restrict__ spk,
    uint32_t* __restrict__ bpk, uint32_t* __restrict__ zpk,
    uint32_t* __restrict__ sfh, uint32_t* __restrict__ bfh,
    uint32_t* __restrict__ zfh) {
  const int which = blockIdx.y;
  const int i2 = blockIdx.x * 256 + threadIdx.x;
  const float* src; uint32_t* d_bf; uint32_t* d_fh; int npair;
  switch (which) {
    case 0: src = y; d_bf = ypk; d_fh = nullptr; npair = M_ * DIN_ / 2; break;
    case 1: src = s; d_bf = spk; d_fh = sfh; npair = M_ * DH_ / 2; break;
    case 2: src = b; d_bf = bpk; d_fh = bfh; npair = M_ * DH_ / 2; break;
    default: src = z; d_bf = zpk; d_fh = zfh; npair = M_ * DH_ / 2; break;
  }
  if (i2 >= npair) return;
  float2 v = *(const float2*)(src + 2 * i2);
  d_bf[2 * i2]     = pack_bf2(v.x);
  d_bf[2 * i2 + 1] = pack_bf2(v.y);
  if (d_fh) d_fh[i2] = pack_f16p(v.x, v.y);
}

// ---- weight transpose; pack=1 -> bf2 words, pack=2 -> f16 pairs ----
struct WEnt { const float* src; uint32_t* dst; int K; int pack; };
struct WTab { WEnt e[12]; };

__global__ void __launch_bounds__(256) transpose_w(const WTab tab) {
  WEnt e = tab.e[blockIdx.z];
  int n0 = blockIdx.x * 32, k0 = blockIdx.y * 32;
  if (k0 >= e.K) return;
  __shared__ float tl[32][33];
  int tx = threadIdx.x, ty = threadIdx.y;
#pragma unroll
  for (int i = 0; i < 32; i += 8)
    tl[ty + i][tx] = e.src[(size_t)(k0 + ty + i) * DH_ + n0 + tx];
  __syncthreads();
  if (e.pack == 1) {
#pragma unroll
    for (int i = 0; i < 32; i += 8)
      e.dst[(size_t)(n0 + ty + i) * e.K + k0 + tx] = pack_bf2(tl[tx][ty + i]);
  } else {
    if (tx < 16) {
#pragma unroll
      for (int i = 0; i < 32; i += 8) {
        int nn = ty + i;
        e.dst[(size_t)(n0 + nn) * (e.K / 2) + k0 / 2 + tx] =
            pack_f16p(tl[2 * tx][nn], tl[2 * tx + 1][nn]);
      }
    }
  }
}

// ---- V transpose: fp32 [token][col] -> f16-pair [col][token/2] ----
__global__ void __launch_bounds__(256) transpose_v(const float* __restrict__ v,
                                                   uint32_t* __restrict__ vt) {
  int z = blockIdx.z, st = z >> 5, bh = z & 31, b = bh >> 4, h = bh & 15;
  int c0 = blockIdx.x * 32, k0 = blockIdx.y * 32;
  __shared__ float tl[32][33];
  int tx = threadIdx.x, ty = threadIdx.y;
  const float* src = v + (size_t)st * NTOK + (size_t)b * S_ * DH_ + h * HD_;
  uint32_t* dst = vt + (size_t)z * (HD_ * S_ / 2);
#pragma unroll
  for (int i = 0; i < 32; i += 8)
    tl[ty + i][tx] = src[(size_t)(k0 + ty + i) * DH_ + c0 + tx];  // tl[tok][col]
  __syncthreads();
  if (tx < 16) {
#pragma unroll
    for (int i = 0; i < 32; i += 8) {
      int cc = ty + i;
      dst[(size_t)(c0 + cc) * (S_ / 2) + k0 / 2 + tx] =
          pack_f16p(tl[2 * tx][cc], tl[2 * tx + 1][cc]);
    }
  }
}

// ---- residual chain ----
__global__ void __launch_bounds__(256) combine_kernel(
    const float* __restrict__ s, const float* __restrict__ b,
    const float* __restrict__ z, const float* __restrict__ ps,
    const float* __restrict__ pb, const float* __restrict__ pz,
    float* __restrict__ os, float* __restrict__ ob, float* __restrict__ oz) {
  size_t i = (size_t)blockIdx.x * 256 + threadIdx.x;
  if (i >= NTOK) return;
  float so = s[i] + ps[i];
  float bo = so + b[i] + pb[i];
  float zo = bo + z[i] + pz[i];
  os[i] = so; ob[i] = bo; oz[i] = zo;
}

// ===========================================================================
extern "C" void kernel_launch(void* const* d_in, const int* in_sizes, int n_in,
                              void* d_out, int out_size) {
  const float* y    = (const float*)d_in[0];
  const float* s    = (const float*)d_in[1];
  const float* b    = (const float*)d_in[2];
  const float* z    = (const float*)d_in[3];
  const float* ba0  = (const float*)d_in[4];
  const float* ba1  = (const float*)d_in[5];
  const float* ba2  = (const float*)d_in[6];
  const float* W[12] = {
      (const float*)d_in[7],  (const float*)d_in[9],  (const float*)d_in[11],
      (const float*)d_in[13], (const float*)d_in[15], (const float*)d_in[17],
      (const float*)d_in[19], (const float*)d_in[21],
      (const float*)d_in[23], (const float*)d_in[25], (const float*)d_in[27],
      (const float*)d_in[29]};
  const float* C[12] = {
      (const float*)d_in[8],  (const float*)d_in[10], (const float*)d_in[12],
      (const float*)d_in[14], (const float*)d_in[16], (const float*)d_in[18],
      (const float*)d_in[20], (const float*)d_in[22],
      (const float*)d_in[24], (const float*)d_in[26], (const float*)d_in[28],
      (const float*)d_in[30]};
  const int KW[12] = {DIN_, DIN_, DIN_, DH_, DH_, DH_, DH_, DH_,
                      DH_, DH_, DH_, DH_};

  float* out   = (float*)d_out;
  float* s_out = out;
  float* b_out = out + NTOK;
  float* z_out = out + 2 * NTOK;
  float* scb   = out + 3 * NTOK;

  uint32_t *gq, *gk, *gof, *gwtf, *gvth, *gyp, *gsp, *gbp, *gzp, *gsf, *gbf, *gzf;
  float *gv, *gp, *gwt;
  cudaGetSymbolAddress((void**)&gq, g_q);
  cudaGetSymbolAddress((void**)&gk, g_k);
  cudaGetSymbolAddress((void**)&gv, g_v);
  cudaGetSymbolAddress((void**)&gof, g_of);
  cudaGetSymbolAddress((void**)&gp, g_p);
  cudaGetSymbolAddress((void**)&gwt, g_wt);
  cudaGetSymbolAddress((void**)&gwtf, g_wtf);
  cudaGetSymbolAddress((void**)&gvth, g_vth);
  cudaGetSymbolAddress((void**)&gyp, g_ypk);
  cudaGetSymbolAddress((void**)&gsp, g_spk);
  cudaGetSymbolAddress((void**)&gbp, g_bpk);
  cudaGetSymbolAddress((void**)&gzp, g_zpk);
  cudaGetSymbolAddress((void**)&gsf, g_sfh);
  cudaGetSymbolAddress((void**)&gbf, g_bfh);
  cudaGetSymbolAddress((void**)&gzf, g_zfh);

  cudaFuncSetAttribute(fused_attn, cudaFuncAttributeMaxDynamicSharedMemorySize,
                       FUSED_SMEM);

  // --- 1a: pack all inputs (one launch) ---
  pack_all<<<dim3(4096, 4), 256>>>(y, s, b, z, gyp, gsp, gbp, gzp,
                                   gsf, gbf, gzf);

  // --- 1b: transpose weights (0..7 bf2, 8..11 f16 pairs) ---
  WTab wt{};
  for (int i = 0; i < 8; i++)
    wt.e[i] = {W[i], (uint32_t*)(gwt + (size_t)i * DH_ * DH_), KW[i], 1};
  for (int i = 8; i < 12; i++)
    wt.e[i] = {W[i], gwtf + (size_t)(i - 8) * (DH_ * DH_ / 2), KW[i], 2};
  transpose_w<<<dim3(32, 32, 12), dim3(32, 8)>>>(wt);

  auto WTp = [&](int i) -> const uint32_t* {
    return (const uint32_t*)(gwt + (size_t)i * DH_ * DH_);
  };
  auto WTf = [&](int i) -> const uint32_t* {
    return gwtf + (size_t)(i - 8) * (DH_ * DH_ / 2);
  };

  // --- 2a: Q + K projections (precise; K/lda/ldb in words = true K) ---
  OpTable tqk{};
  auto setp = [&](int idx, uint32_t* Cp, int K, int nt,
                  const uint32_t* A0, int w0,
                  const uint32_t* A1 = nullptr, int w1 = -1,
                  const uint32_t* A2 = nullptr, int w2 = -1) {
    Op& o = tqk.op[idx];
    o.C = (float*)Cp; o.K = K; o.nt = nt; o.lda = K; o.ldb = K; o.ldc = DH_;
    o.t[0] = {A0, WTp(w0), C[w0]};
    if (nt > 1) o.t[1] = {A1, WTp(w1), C[w1]};
    if (nt > 2) o.t[2] = {A2, WTp(w2), C[w2]};
  };
  setp(0, gq + 0 * NTOK, DIN_, 1, gyp, 0);
  setp(1, gq + 1 * NTOK, DIN_, 1, gyp, 1);
  setp(2, gq + 2 * NTOK, DIN_, 1, gyp, 2);
  setp(3, gk + 0 * NTOK, DH_, 2, gsp, 3, gbp, 4);
  setp(4, gk + 1 * NTOK, DH_, 3, gbp, 6, gsp, 4, gzp, 5);
  setp(5, gk + 2 * NTOK, DH_, 2, gzp, 7, gbp, 5);
  proj_precise<<<dim3(8, 16, 6), 256>>>(tqk);

  // --- 2b: V projections (f16; K in words = true K / 2) ---
  OpTable tv{};
  const uint32_t* fin[3] = {gsf, gbf, gzf};
  for (int i = 0; i < 3; i++) {
    Op& o = tv.op[i];
    o.C = gv + (size_t)i * NTOK; o.K = DH_ / 2; o.nt = 1;
    o.lda = DH_ / 2; o.ldb = DH_ / 2; o.ldc = DH_;
    o.t[0] = {fin[i], WTf(8 + i), C[8 + i]};
  }
  proj_f16<<<dim3(8, 16, 3), 256>>>(tv);

  // --- 3: V transpose -> f16-pair [col][token/2] ---
  transpose_v<<<dim3(2, 32, 96), dim3(32, 8)>>>(gv, gvth);

  // --- 4: fused attention ---
  fused_attn<<<dim3(8, 96), 256, FUSED_SMEM>>>(gq, gk, gvth, ba0, ba1, ba2,
                                               scb, gof);

  // --- 5: output projections (f16) ---
  OpTable to{};
  for (int i = 0; i < 3; i++) {
    Op& o = to.op[i];
    o.C = gp + (size_t)i * NTOK; o.K = DH_ / 2; o.nt = 1;
    o.lda = DH_ / 2; o.ldb = DH_ / 2; o.ldc = DH_;
    o.t[0] = {gof + (size_t)i * (NTOK / 2), WTf(11), C[11]};
  }
  proj_f16<<<dim3(8, 16, 3), 256>>>(to);

  // --- 6: residual chain ---
  combine_kernel<<<(int)((NTOK + 255) / 256), 256>>>(
      s, b, z, gp + 0 * NTOK, gp + 1 * NTOK, gp + 2 * NTOK,
      s_out, b_out, z_out);
}

// round 8
// speedup vs baseline: 3.8888x; 1.0070x over previous
#include <cuda_runtime.h>
#include <cuda_bf16.h>
#include <cuda_fp16.h>
#include <cstdint>
#include <math.h>

// ===========================================================================
// MarkovBlanketAttention on sm_103 — R7: ldmatrix fragment loads everywhere.
// Precise chain (Q/K proj, QK^T): packed-bf16x2 2-MMA.
// Fast chain (V proj, PV, out proj): packed-f16-pair single MMA.
// ===========================================================================

namespace {
constexpr int B_   = 2;
constexpr int S_   = 1024;
constexpr int DIN_ = 512;
constexpr int DH_  = 1024;
constexpr int H_   = 16;
constexpr int HD_  = 64;
constexpr int M_   = B_ * S_;
constexpr size_t NTOK = (size_t)M_ * DH_;
constexpr size_t NSC  = (size_t)B_ * H_ * S_ * S_;
}

// ---- scratch (device globals) ----
__device__ uint32_t g_q[3][NTOK];
__device__ uint32_t g_k[3][NTOK];
__device__ float    g_v[3][NTOK];
__device__ uint32_t g_of[3][NTOK / 2];
__device__ float    g_p[3][NTOK];
__device__ float    g_wt[8][DH_ * DH_];
__device__ uint32_t g_wtf[4][DH_ * DH_ / 2];
__device__ uint32_t g_vth[96][HD_ * S_ / 2];
__device__ uint32_t g_ypk[M_ * DIN_];
__device__ uint32_t g_spk[M_ * DH_];
__device__ uint32_t g_bpk[M_ * DH_];
__device__ uint32_t g_zpk[M_ * DH_];
__device__ uint32_t g_sfh[M_ * DH_ / 2];
__device__ uint32_t g_bfh[M_ * DH_ / 2];
__device__ uint32_t g_zfh[M_ * DH_ / 2];

// ---------------------------------------------------------------------------
// helpers
// ---------------------------------------------------------------------------
__device__ __forceinline__ uint32_t smem_u32(const void* p) {
  uint32_t a;
  asm("{ .reg .u64 t; cvta.to.shared.u64 t, %1; cvt.u32.u64 %0, t; }"
      : "=r"(a) : "l"(p));
  return a;
}
__device__ __forceinline__ void cp16(void* smem, const void* g) {
  asm volatile("cp.async.cg.shared.global [%0], [%1], 16;"
               :: "r"(smem_u32(smem)), "l"(g));
}
__device__ __forceinline__ void cp_commit() {
  asm volatile("cp.async.commit_group;" ::: "memory");
}
template <int N>
__device__ __forceinline__ void cp_wait() {
  asm volatile("cp.async.wait_group %0;" :: "n"(N) : "memory");
}
__device__ __forceinline__ void ldsm4(uint32_t* r, uint32_t addr) {
  asm volatile(
      "ldmatrix.sync.aligned.m8n8.x4.shared.b16 {%0,%1,%2,%3}, [%4];"
      : "=r"(r[0]), "=r"(r[1]), "=r"(r[2]), "=r"(r[3]) : "r"(addr));
}
__device__ __forceinline__ void mma_bf16_k16(float* c, const uint32_t* a,
                                             const uint32_t* b) {
  asm volatile(
      "mma.sync.aligned.m16n8k16.row.col.f32.bf16.bf16.f32 "
      "{%0,%1,%2,%3}, {%4,%5,%6,%7}, {%8,%9}, {%0,%1,%2,%3};"
      : "+f"(c[0]), "+f"(c[1]), "+f"(c[2]), "+f"(c[3])
      : "r"(a[0]), "r"(a[1]), "r"(a[2]), "r"(a[3]), "r"(b[0]), "r"(b[1]));
}
__device__ __forceinline__ void mma_f16_k16(float* c, const uint32_t* a,
                                            const uint32_t* b) {
  asm volatile(
      "mma.sync.aligned.m16n8k16.row.col.f32.f16.f16.f32 "
      "{%0,%1,%2,%3}, {%4,%5,%6,%7}, {%8,%9}, {%0,%1,%2,%3};"
      : "+f"(c[0]), "+f"(c[1]), "+f"(c[2]), "+f"(c[3])
      : "r"(a[0]), "r"(a[1]), "r"(a[2]), "r"(a[3]), "r"(b[0]), "r"(b[1]));
}
__device__ __forceinline__ uint32_t pack_bf2(float v) {
  __nv_bfloat16 h = __float2bfloat16_rn(v);
  float fh = __bfloat162float(h);
  __nv_bfloat16 l = __float2bfloat16_rn(v - fh);
  return (uint32_t)__bfloat16_as_ushort(h) |
         ((uint32_t)__bfloat16_as_ushort(l) << 16);
}
__device__ __forceinline__ uint32_t pack_f16p(float a, float b) {
  __half2 h = __floats2half2_rn(a, b);
  return *(uint32_t*)&h;
}

// ---------------------------------------------------------------------------
// GEMM core.  MODE 0 = fast f16-pair; MODE 1 = precise bf16x2 2-MMA.
// op.K, lda, ldb in WORDS.
// ---------------------------------------------------------------------------
struct Term { const uint32_t* A; const uint32_t* W; const float* bias; };
struct Op   { Term t[3]; float* C; int nt; int K; int lda; int ldb; int ldc; };
struct OpTable { Op op[9]; };

template <int BN, int MODE, bool PACKOUT>
__device__ __forceinline__ void gemm_core(const Op& op) {
  constexpr int BK = 16;
  constexpr int PITCH = 20;
  constexpr int WN = BN / 2;
  constexpr int NT = WN / 8;
  __shared__ uint32_t As[2][128 * PITCH];
  __shared__ uint32_t Bs[2][BN * PITCH];

  const int t = threadIdx.x;
  const int wid = t >> 5, lane = t & 31;
  const int warp_m = wid & 3;
  const int wn = wid >> 2;
  const int gid = lane >> 2, qid = lane & 3;

  const int bm = blockIdx.y * 128;
  const int bn = blockIdx.x * BN;
  const int cpt = op.K / BK;
  const int total = op.nt * cpt;

  // ldmatrix lane offsets (bytes)
  const uint32_t asb = smem_u32(As);
  const uint32_t bsb = smem_u32(Bs);
  const uint32_t a_off =
      (((lane & 15) * PITCH) + ((lane >> 4) << 2)) * 4;
  const uint32_t b_off =
      ((((lane & 7) + ((lane >> 4) << 3)) * PITCH) + (((lane >> 3) & 1) << 2)) * 4;

  float acc[2][NT][4];
#pragma unroll
  for (int mt = 0; mt < 2; mt++)
#pragma unroll
    for (int nt = 0; nt < NT; nt++)
#pragma unroll
      for (int j = 0; j < 4; j++) acc[mt][nt][j] = 0.f;

  auto load_chunk = [&](int c, int buf) {
    const int term = c / cpt;
    const int k0 = (c - term * cpt) * BK;
    const uint32_t* __restrict__ A = op.t[term].A;
    const uint32_t* __restrict__ W = op.t[term].W;
#pragma unroll
    for (int i = 0; i < 2; i++) {
      int f = t + i * 256;
      int r = f >> 2, c4 = (f & 3) * 4;
      cp16(&As[buf][r * PITCH + c4], A + (size_t)(bm + r) * op.lda + k0 + c4);
    }
#pragma unroll
    for (int i = 0; i < BN / 64; i++) {
      int f = t + i * 256;
      int r = f >> 2, c4 = (f & 3) * 4;
      cp16(&Bs[buf][r * PITCH + c4], W + (size_t)(bn + r) * op.ldb + k0 + c4);
    }
  };

  load_chunk(0, 0);
  cp_commit();

  for (int c = 0; c < total; c++) {
    const int buf = c & 1;
    if (c + 1 < total) load_chunk(c + 1, (c + 1) & 1);
    cp_commit();
    cp_wait<1>();
    __syncthreads();

#pragma unroll
    for (int kk = 0; kk < BK; kk += 8) {
      uint32_t af[2][4];
#pragma unroll
      for (int mt = 0; mt < 2; mt++) {
        uint32_t ad = asb + a_off +
            (uint32_t)((buf * 128 * PITCH + (warp_m * 32 + mt * 16) * PITCH + kk) * 4);
        ldsm4(af[mt], ad);
      }
#pragma unroll
      for (int nt2 = 0; nt2 < NT / 2; nt2++) {
        uint32_t bf[4];
        uint32_t bd = bsb + b_off +
            (uint32_t)((buf * BN * PITCH + (wn * WN + nt2 * 16) * PITCH + kk) * 4);
        ldsm4(bf, bd);
#pragma unroll
        for (int half = 0; half < 2; half++) {
          const int nt = nt2 * 2 + half;
          uint32_t u0 = bf[half * 2], u1 = bf[half * 2 + 1];
          if (MODE == 1) {
            uint32_t bh[2] = {__byte_perm(u0, 0, 0x1010),
                              __byte_perm(u1, 0, 0x1010)};
            uint32_t bl[2] = {__byte_perm(u0, 0, 0x3232),
                              __byte_perm(u1, 0, 0x3232)};
#pragma unroll
            for (int mt = 0; mt < 2; mt++) {
              mma_bf16_k16(acc[mt][nt], af[mt], bh);
              mma_bf16_k16(acc[mt][nt], af[mt], bl);
            }
          } else {
            uint32_t br[2] = {u0, u1};
#pragma unroll
            for (int mt = 0; mt < 2; mt++) mma_f16_k16(acc[mt][nt], af[mt], br);
          }
        }
      }
    }
    __syncthreads();
  }

#pragma unroll
  for (int mt = 0; mt < 2; mt++) {
    int row0 = bm + warp_m * 32 + mt * 16 + gid;
#pragma unroll
    for (int nt = 0; nt < NT; nt++) {
      int col = bn + wn * WN + nt * 8 + qid * 2;
      float b0 = 0.f, b1 = 0.f;
      if (op.t[0].bias) {
        for (int tt = 0; tt < op.nt; tt++) {
          b0 += op.t[tt].bias[col];
          b1 += op.t[tt].bias[col + 1];
        }
      }
      float v00 = acc[mt][nt][0] + b0, v01 = acc[mt][nt][1] + b1;
      float v10 = acc[mt][nt][2] + b0, v11 = acc[mt][nt][3] + b1;
      if (PACKOUT) {
        uint32_t* Cp = (uint32_t*)op.C;
        uint2 p0 = {pack_bf2(v00), pack_bf2(v01)};
        uint2 p1 = {pack_bf2(v10), pack_bf2(v11)};
        *(uint2*)(Cp + (size_t)row0 * op.ldc + col) = p0;
        *(uint2*)(Cp + (size_t)(row0 + 8) * op.ldc + col) = p1;
      } else {
        *(float2*)(op.C + (size_t)row0 * op.ldc + col) = {v00, v01};
        *(float2*)(op.C + (size_t)(row0 + 8) * op.ldc + col) = {v10, v11};
      }
    }
  }
}

__global__ void __launch_bounds__(256) proj_precise(const OpTable tab) {
  gemm_core<128, 1, true>(tab.op[blockIdx.z]);
}
__global__ void __launch_bounds__(256) proj_f16(const OpTable tab) {
  gemm_core<128, 0, false>(tab.op[blockIdx.z]);
}

// ---------------------------------------------------------------------------
// Fused attention (ldmatrix fragment loads).
// ---------------------------------------------------------------------------
namespace {
constexpr int TP = 68;
constexpr int QK_W = 128 * TP;
constexpr int VT_W = 64 * TP;
constexpr int FUSED_SMEM = (3 * QK_W + 2 * VT_W + QK_W) * 4;  // 174080 B
}

__global__ void __launch_bounds__(256) fused_attn(
    const uint32_t* __restrict__ qb, const uint32_t* __restrict__ kb,
    const uint32_t* __restrict__ vtb, const float* __restrict__ bias0,
    const float* __restrict__ bias1, const float* __restrict__ bias2,
    float* __restrict__ score_out, uint32_t* __restrict__ ofb) {
  extern __shared__ uint32_t sm[];
  uint32_t* Qs = sm;
  uint32_t* Ks = sm + QK_W;
  uint32_t* VT = sm + 3 * QK_W;
  uint32_t* Ps = sm + 3 * QK_W + 2 * VT_W;

  const int zz = blockIdx.y;
  const int st = zz >> 5, bh = zz & 31, b = bh >> 4, h = bh & 15;
  const int q0 = blockIdx.x * 128;

  const uint32_t* qp = qb + (size_t)st * NTOK + (size_t)(b * S_ + q0) * DH_ + h * HD_;
  const uint32_t* kp = kb + (size_t)st * NTOK + (size_t)b * S_ * DH_ + h * HD_;
  const uint32_t* vtp = vtb + (size_t)zz * (HD_ * S_ / 2);
  const float* bias = (st == 0) ? bias0 : (st == 1) ? bias1 : bias2;
  const float* brow = bias + (size_t)bh * S_ * S_ + (size_t)q0 * S_;
  float* srow = score_out + (size_t)st * NSC + (size_t)bh * S_ * S_ + (size_t)q0 * S_;
  uint32_t* ofp = ofb + (size_t)st * (NTOK / 2) + (size_t)(b * S_ + q0) * (DH_ / 2) + h * (HD_ / 2);

  const int t = threadIdx.x;
  const int w = t >> 5, lane = t & 31;
  const int gid = lane >> 2, qid = lane & 3;
  const int r0 = w * 16 + gid;

  const uint32_t smb = smem_u32(sm);
  const uint32_t a_off =
      (((lane & 15) * TP) + ((lane >> 4) << 2)) * 4;        // A-style (16 rows)
  const uint32_t b_off =
      ((((lane & 7) + ((lane >> 4) << 3)) * TP) + (((lane >> 3) & 1) << 2)) * 4;

  auto load_q = [&]() {
#pragma unroll
    for (int i = 0; i < 8; i++) {
      int f = t + i * 256;
      int r = f >> 4, c4 = (f & 15) * 4;
      cp16(&Qs[r * TP + c4], qp + (size_t)r * DH_ + c4);
    }
  };
  auto load_kv = [&](int kbk, int buf) {
#pragma unroll
    for (int i = 0; i < 8; i++) {
      int f = t + i * 256;
      int r = f >> 4, c4 = (f & 15) * 4;
      cp16(&Ks[buf * QK_W + r * TP + c4],
           kp + (size_t)(kbk * 128 + r) * DH_ + c4);
    }
#pragma unroll
    for (int i = 0; i < 4; i++) {
      int f = t + i * 256;
      int r = f >> 4, c4 = (f & 15) * 4;
      cp16(&VT[buf * VT_W + r * TP + c4],
           vtp + (size_t)r * (S_ / 2) + kbk * 64 + c4);
    }
  };

  load_q();
  load_kv(0, 0);
  cp_commit();
  load_kv(1, 1);
  cp_commit();

  float m0 = -1e30f, m1 = -1e30f, l0 = 0.f, l1 = 0.f;
  float oacc[8][4];
#pragma unroll
  for (int j = 0; j < 8; j++)
#pragma unroll
    for (int q = 0; q < 4; q++) oacc[j][q] = 0.f;

  const uint32_t q_base = smb + a_off + (uint32_t)(w * 16 * TP * 4);
  const uint32_t p_base = smb + a_off +
      (uint32_t)((3 * QK_W + 2 * VT_W + w * 16 * TP) * 4);

  for (int it = 0; it < 8; it++) {
    const int buf = it & 1;
    cp_wait<1>();
    __syncthreads();

    // ---- scores: precise bf16x2 2-MMA, ldmatrix fragments ----
    float acc[16][4];
#pragma unroll
    for (int nt = 0; nt < 16; nt++)
#pragma unroll
      for (int q = 0; q < 4; q++) acc[nt][q] = 0.f;

#pragma unroll
    for (int kk = 0; kk < 64; kk += 8) {
      uint32_t af[4];
      ldsm4(af, q_base + (uint32_t)(kk * 4));
#pragma unroll
      for (int nt2 = 0; nt2 < 8; nt2++) {
        uint32_t kf[4];
        uint32_t kd = smb + b_off +
            (uint32_t)((QK_W + buf * QK_W + nt2 * 16 * TP + kk) * 4);
        ldsm4(kf, kd);
#pragma unroll
        for (int half = 0; half < 2; half++) {
          const int nt = nt2 * 2 + half;
          uint32_t u0 = kf[half * 2], u1 = kf[half * 2 + 1];
          uint32_t bh2[2] = {__byte_perm(u0, 0, 0x1010), __byte_perm(u1, 0, 0x1010)};
          uint32_t bl2[2] = {__byte_perm(u0, 0, 0x3232), __byte_perm(u1, 0, 0x3232)};
          mma_bf16_k16(acc[nt], af, bh2);
          mma_bf16_k16(acc[nt], af, bl2);
        }
      }
    }

    // ---- raw scores out, add bias ----
    const int cbase = it * 128;
#pragma unroll
    for (int nt = 0; nt < 16; nt++) {
      int col = cbase + nt * 8 + qid * 2;
      *(float2*)(srow + (size_t)(r0)     * S_ + col) = {acc[nt][0], acc[nt][1]};
      *(float2*)(srow + (size_t)(r0 + 8) * S_ + col) = {acc[nt][2], acc[nt][3]};
      float2 bv0 = *(const float2*)(brow + (size_t)(r0)     * S_ + col);
      float2 bv1 = *(const float2*)(brow + (size_t)(r0 + 8) * S_ + col);
      acc[nt][0] += bv0.x; acc[nt][1] += bv0.y;
      acc[nt][2] += bv1.x; acc[nt][3] += bv1.y;
    }

    // ---- online softmax ----
    float mt0 = -1e30f, mt1 = -1e30f;
#pragma unroll
    for (int nt = 0; nt < 16; nt++) {
      mt0 = fmaxf(mt0, fmaxf(acc[nt][0], acc[nt][1]));
      mt1 = fmaxf(mt1, fmaxf(acc[nt][2], acc[nt][3]));
    }
    mt0 = fmaxf(mt0, __shfl_xor_sync(0xffffffffu, mt0, 1));
    mt0 = fmaxf(mt0, __shfl_xor_sync(0xffffffffu, mt0, 2));
    mt1 = fmaxf(mt1, __shfl_xor_sync(0xffffffffu, mt1, 1));
    mt1 = fmaxf(mt1, __shfl_xor_sync(0xffffffffu, mt1, 2));

    float m0n = fmaxf(m0, mt0), m1n = fmaxf(m1, mt1);
    float sc0 = __expf(m0 - m0n), sc1 = __expf(m1 - m1n);
    m0 = m0n; m1 = m1n;
    l0 *= sc0; l1 *= sc1;
#pragma unroll
    for (int j = 0; j < 8; j++) {
      oacc[j][0] *= sc0; oacc[j][1] *= sc0;
      oacc[j][2] *= sc1; oacc[j][3] *= sc1;
    }

    // ---- exp -> Ps (f16 pairs) ----
    float ts0 = 0.f, ts1 = 0.f;
#pragma unroll
    for (int nt = 0; nt < 16; nt++) {
      float p00 = __expf(acc[nt][0] - m0);
      float p01 = __expf(acc[nt][1] - m0);
      float p10 = __expf(acc[nt][2] - m1);
      float p11 = __expf(acc[nt][3] - m1);
      ts0 += p00 + p01; ts1 += p10 + p11;
      Ps[(r0)     * TP + nt * 4 + qid] = pack_f16p(p00, p01);
      Ps[(r0 + 8) * TP + nt * 4 + qid] = pack_f16p(p10, p11);
    }
    ts0 += __shfl_xor_sync(0xffffffffu, ts0, 1);
    ts0 += __shfl_xor_sync(0xffffffffu, ts0, 2);
    ts1 += __shfl_xor_sync(0xffffffffu, ts1, 1);
    ts1 += __shfl_xor_sync(0xffffffffu, ts1, 2);
    l0 += ts0; l1 += ts1;
    __syncwarp();

    // ---- PV: f16 k16 via ldmatrix ----
#pragma unroll
    for (int kw = 0; kw < 64; kw += 8) {
      uint32_t ap[4];
      ldsm4(ap, p_base + (uint32_t)(kw * 4));
#pragma unroll
      for (int j2 = 0; j2 < 4; j2++) {
        uint32_t vf[4];
        uint32_t vd = smb + b_off +
            (uint32_t)((3 * QK_W + buf * VT_W + j2 * 16 * TP + kw) * 4);
        ldsm4(vf, vd);
        mma_f16_k16(oacc[j2 * 2],     ap, vf);
        mma_f16_k16(oacc[j2 * 2 + 1], ap, vf + 2);
      }
    }
    __syncthreads();

    if (it + 2 < 8) load_kv(it + 2, buf);
    cp_commit();
  }

  // ---- finalize ----
  float inv0 = 1.f / l0, inv1 = 1.f / l1;
#pragma unroll
  for (int j = 0; j < 8; j++) {
    int cw = j * 4 + qid;
    ofp[(size_t)(r0)     * (DH_ / 2) + cw] =
        pack_f16p(oacc[j][0] * inv0, oacc[j][1] * inv0);
    ofp[(size_t)(r0 + 8) * (DH_ / 2) + cw] =
        pack_f16p(oacc[j][2] * inv1, oacc[j][3] * inv1);
  }
}

// ---- fused input packing ----
__global__ void __launch_bounds__(256) pack_all(
    const float* __restrict__ y, const float* __restrict__ s,
    const float* __restrict__ b, const float* __restrict__ z,
    uint32_t* __restrict__ ypk, uint32_t* __restrict__ spk,
    uint32_t* __restrict__ bpk, uint32_t* __restrict__ zpk,
    uint32_t* __restrict__ sfh, uint32_t* __restrict__ bfh,
    uint32_t* __restrict__ zfh) {
  const int which = blockIdx.y;
  const int i2 = blockIdx.x * 256 + threadIdx.x;
  const float* src; uint32_t* d_bf; uint32_t* d_fh; int npair;
  switch (which) {
    case 0: src = y; d_bf = ypk; d_fh = nullptr; npair = M_ * DIN_ / 2; break;
    case 1: src = s; d_bf = spk; d_fh = sfh; npair = M_ * DH_ / 2; break;
    case 2: src = b; d_bf = bpk; d_fh = bfh; npair = M_ * DH_ / 2; break;
    default: src = z; d_bf = zpk; d_fh = zfh; npair = M_ * DH_ / 2; break;
  }
  if (i2 >= npair) return;
  float2 v = *(const float2*)(src + 2 * i2);
  d_bf[2 * i2]     = pack_bf2(v.x);
  d_bf[2 * i2 + 1] = pack_bf2(v.y);
  if (d_fh) d_fh[i2] = pack_f16p(v.x, v.y);
}

// ---- weight transpose ----
struct WEnt { const float* src; uint32_t* dst; int K; int pack; };
struct WTab { WEnt e[12]; };

__global__ void __launch_bounds__(256) transpose_w(const WTab tab) {
  WEnt e = tab.e[blockIdx.z];
  int n0 = blockIdx.x * 32, k0 = blockIdx.y * 32;
  if (k0 >= e.K) return;
  __shared__ float tl[32][33];
  int tx = threadIdx.x, ty = threadIdx.y;
#pragma unroll
  for (int i = 0; i < 32; i += 8)
    tl[ty + i][tx] = e.src[(size_t)(k0 + ty + i) * DH_ + n0 + tx];
  __syncthreads();
  if (e.pack == 1) {
#pragma unroll
    for (int i = 0; i < 32; i += 8)
      e.dst[(size_t)(n0 + ty + i) * e.K + k0 + tx] = pack_bf2(tl[tx][ty + i]);
  } else {
    if (tx < 16) {
#pragma unroll
      for (int i = 0; i < 32; i += 8) {
        int nn = ty + i;
        e.dst[(size_t)(n0 + nn) * (e.K / 2) + k0 / 2 + tx] =
            pack_f16p(tl[2 * tx][nn], tl[2 * tx + 1][nn]);
      }
    }
  }
}

// ---- V transpose ----
__global__ void __launch_bounds__(256) transpose_v(const float* __restrict__ v,
                                                   uint32_t* __restrict__ vt) {
  int z = blockIdx.z, st = z >> 5, bh = z & 31, b = bh >> 4, h = bh & 15;
  int c0 = blockIdx.x * 32, k0 = blockIdx.y * 32;
  __shared__ float tl[32][33];
  int tx = threadIdx.x, ty = threadIdx.y;
  const float* src = v + (size_t)st * NTOK + (size_t)b * S_ * DH_ + h * HD_;
  uint32_t* dst = vt + (size_t)z * (HD_ * S_ / 2);
#pragma unroll
  for (int i = 0; i < 32; i += 8)
    tl[ty + i][tx] = src[(size_t)(k0 + ty + i) * DH_ + c0 + tx];
  __syncthreads();
  if (tx < 16) {
#pragma unroll
    for (int i = 0; i < 32; i += 8) {
      int cc = ty + i;
      dst[(size_t)(c0 + cc) * (S_ / 2) + k0 / 2 + tx] =
          pack_f16p(tl[2 * tx][cc], tl[2 * tx + 1][cc]);
    }
  }
}

// ---- residual chain ----
__global__ void __launch_bounds__(256) combine_kernel(
    const float* __restrict__ s, const float* __restrict__ b,
    const float* __restrict__ z, const float* __restrict__ ps,
    const float* __restrict__ pb, const float* __restrict__ pz,
    float* __restrict__ os, float* __restrict__ ob, float* __restrict__ oz) {
  size_t i = (size_t)blockIdx.x * 256 + threadIdx.x;
  if (i >= NTOK) return;
  float so = s[i] + ps[i];
  float bo = so + b[i] + pb[i];
  float zo = bo + z[i] + pz[i];
  os[i] = so; ob[i] = bo; oz[i] = zo;
}

// ===========================================================================
extern "C" void kernel_launch(void* const* d_in, const int* in_sizes, int n_in,
                              void* d_out, int out_size) {
  const float* y    = (const float*)d_in[0];
  const float* s    = (const float*)d_in[1];
  const float* b    = (const float*)d_in[2];
  const float* z    = (const float*)d_in[3];
  const float* ba0  = (const float*)d_in[4];
  const float* ba1  = (const float*)d_in[5];
  const float* ba2  = (const float*)d_in[6];
  const float* W[12] = {
      (const float*)d_in[7],  (const float*)d_in[9],  (const float*)d_in[11],
      (const float*)d_in[13], (const float*)d_in[15], (const float*)d_in[17],
      (const float*)d_in[19], (const float*)d_in[21],
      (const float*)d_in[23], (const float*)d_in[25], (const float*)d_in[27],
      (const float*)d_in[29]};
  const float* C[12] = {
      (const float*)d_in[8],  (const float*)d_in[10], (const float*)d_in[12],
      (const float*)d_in[14], (const float*)d_in[16], (const float*)d_in[18],
      (const float*)d_in[20], (const float*)d_in[22],
      (const float*)d_in[24], (const float*)d_in[26], (const float*)d_in[28],
      (const float*)d_in[30]};
  const int KW[12] = {DIN_, DIN_, DIN_, DH_, DH_, DH_, DH_, DH_,
                      DH_, DH_, DH_, DH_};

  float* out   = (float*)d_out;
  float* s_out = out;
  float* b_out = out + NTOK;
  float* z_out = out + 2 * NTOK;
  float* scb   = out + 3 * NTOK;

  uint32_t *gq, *gk, *gof, *gwtf, *gvth, *gyp, *gsp, *gbp, *gzp, *gsf, *gbf, *gzf;
  float *gv, *gp, *gwt;
  cudaGetSymbolAddress((void**)&gq, g_q);
  cudaGetSymbolAddress((void**)&gk, g_k);
  cudaGetSymbolAddress((void**)&gv, g_v);
  cudaGetSymbolAddress((void**)&gof, g_of);
  cudaGetSymbolAddress((void**)&gp, g_p);
  cudaGetSymbolAddress((void**)&gwt, g_wt);
  cudaGetSymbolAddress((void**)&gwtf, g_wtf);
  cudaGetSymbolAddress((void**)&gvth, g_vth);
  cudaGetSymbolAddress((void**)&gyp, g_ypk);
  cudaGetSymbolAddress((void**)&gsp, g_spk);
  cudaGetSymbolAddress((void**)&gbp, g_bpk);
  cudaGetSymbolAddress((void**)&gzp, g_zpk);
  cudaGetSymbolAddress((void**)&gsf, g_sfh);
  cudaGetSymbolAddress((void**)&gbf, g_bfh);
  cudaGetSymbolAddress((void**)&gzf, g_zfh);

  cudaFuncSetAttribute(fused_attn, cudaFuncAttributeMaxDynamicSharedMemorySize,
                       FUSED_SMEM);

  // --- 1a: pack all inputs ---
  pack_all<<<dim3(4096, 4), 256>>>(y, s, b, z, gyp, gsp, gbp, gzp,
                                   gsf, gbf, gzf);

  // --- 1b: transpose weights ---
  WTab wt{};
  for (int i = 0; i < 8; i++)
    wt.e[i] = {W[i], (uint32_t*)(gwt + (size_t)i * DH_ * DH_), KW[i], 1};
  for (int i = 8; i < 12; i++)
    wt.e[i] = {W[i], gwtf + (size_t)(i - 8) * (DH_ * DH_ / 2), KW[i], 2};
  transpose_w<<<dim3(32, 32, 12), dim3(32, 8)>>>(wt);

  auto WTp = [&](int i) -> const uint32_t* {
    return (const uint32_t*)(gwt + (size_t)i * DH_ * DH_);
  };
  auto WTf = [&](int i) -> const uint32_t* {
    return gwtf + (size_t)(i - 8) * (DH_ * DH_ / 2);
  };

  // --- 2a: Q + K projections (precise) ---
  OpTable tqk{};
  auto setp = [&](int idx, uint32_t* Cp, int K, int nt,
                  const uint32_t* A0, int w0,
                  const uint32_t* A1 = nullptr, int w1 = -1,
                  const uint32_t* A2 = nullptr, int w2 = -1) {
    Op& o = tqk.op[idx];
    o.C = (float*)Cp; o.K = K; o.nt = nt; o.lda = K; o.ldb = K; o.ldc = DH_;
    o.t[0] = {A0, WTp(w0), C[w0]};
    if (nt > 1) o.t[1] = {A1, WTp(w1), C[w1]};
    if (nt > 2) o.t[2] = {A2, WTp(w2), C[w2]};
  };
  setp(0, gq + 0 * NTOK, DIN_, 1, gyp, 0);
  setp(1, gq + 1 * NTOK, DIN_, 1, gyp, 1);
  setp(2, gq + 2 * NTOK, DIN_, 1, gyp, 2);
  setp(3, gk + 0 * NTOK, DH_, 2, gsp, 3, gbp, 4);
  setp(4, gk + 1 * NTOK, DH_, 3, gbp, 6, gsp, 4, gzp, 5);
  setp(5, gk + 2 * NTOK, DH_, 2, gzp, 7, gbp, 5);
  proj_precise<<<dim3(8, 16, 6), 256>>>(tqk);

  // --- 2b: V projections (f16) ---
  OpTable tv{};
  const uint32_t* fin[3] = {gsf, gbf, gzf};
  for (int i = 0; i < 3; i++) {
    Op& o = tv.op[i];
    o.C = gv + (size_t)i * NTOK; o.K = DH_ / 2; o.nt = 1;
    o.lda = DH_ / 2; o.ldb = DH_ / 2; o.ldc = DH_;
    o.t[0] = {fin[i], WTf(8 + i), C[8 + i]};
  }
  proj_f16<<<dim3(8, 16, 3), 256>>>(tv);

  // --- 3: V transpose ---
  transpose_v<<<dim3(2, 32, 96), dim3(32, 8)>>>(gv, gvth);

  // --- 4: fused attention ---
  fused_attn<<<dim3(8, 96), 256, FUSED_SMEM>>>(gq, gk, gvth, ba0, ba1, ba2,
                                               scb, gof);

  // --- 5: output projections (f16) ---
  OpTable to{};
  for (int i = 0; i < 3; i++) {
    Op& o = to.op[i];
    o.C = gp + (size_t)i * NTOK; o.K = DH_ / 2; o.nt = 1;
    o.lda = DH_ / 2; o.ldb = DH_ / 2; o.ldc = DH_;
    o.t[0] = {gof + (size_t)i * (NTOK / 2), WTf(11), C[11]};
  }
  proj_f16<<<dim3(8, 16, 3), 256>>>(to);

  // --- 6: residual chain ---
  combine_kernel<<<(int)((NTOK + 255) / 256), 256>>>(
      s, b, z, gp + 0 * NTOK, gp + 1 * NTOK, gp + 2 * NTOK,
      s_out, b_out, z_out);
}

// round 9
// speedup vs baseline: 3.9443x; 1.0143x over previous
#include <cuda_runtime.h>
#include <cuda_bf16.h>
#include <cuda_fp16.h>
#include <cstdint>
#include <math.h>

// ===========================================================================
// MarkovBlanketAttention on sm_103 — R8: BK=32-word GEMM chunks (half the
// barriers), dynamic smem double buffer, ldmatrix fragments.
// Precise chain (Q/K proj, QK^T): packed-bf16x2 2-MMA.
// Fast chain (V proj, PV, out proj): packed-f16-pair single MMA.
// ===========================================================================

namespace {
constexpr int B_   = 2;
constexpr int S_   = 1024;
constexpr int DIN_ = 512;
constexpr int DH_  = 1024;
constexpr int H_   = 16;
constexpr int HD_  = 64;
constexpr int M_   = B_ * S_;
constexpr size_t NTOK = (size_t)M_ * DH_;
constexpr size_t NSC  = (size_t)B_ * H_ * S_ * S_;
}

// ---- scratch (device globals) ----
__device__ uint32_t g_q[3][NTOK];
__device__ uint32_t g_k[3][NTOK];
__device__ float    g_v[3][NTOK];
__device__ uint32_t g_of[3][NTOK / 2];
__device__ float    g_p[3][NTOK];
__device__ float    g_wt[8][DH_ * DH_];
__device__ uint32_t g_wtf[4][DH_ * DH_ / 2];
__device__ uint32_t g_vth[96][HD_ * S_ / 2];
__device__ uint32_t g_ypk[M_ * DIN_];
__device__ uint32_t g_spk[M_ * DH_];
__device__ uint32_t g_bpk[M_ * DH_];
__device__ uint32_t g_zpk[M_ * DH_];
__device__ uint32_t g_sfh[M_ * DH_ / 2];
__device__ uint32_t g_bfh[M_ * DH_ / 2];
__device__ uint32_t g_zfh[M_ * DH_ / 2];

// ---------------------------------------------------------------------------
// helpers
// ---------------------------------------------------------------------------
__device__ __forceinline__ uint32_t smem_u32(const void* p) {
  uint32_t a;
  asm("{ .reg .u64 t; cvta.to.shared.u64 t, %1; cvt.u32.u64 %0, t; }"
      : "=r"(a) : "l"(p));
  return a;
}
__device__ __forceinline__ void cp16(void* smem, const void* g) {
  asm volatile("cp.async.cg.shared.global [%0], [%1], 16;"
               :: "r"(smem_u32(smem)), "l"(g));
}
__device__ __forceinline__ void cp_commit() {
  asm volatile("cp.async.commit_group;" ::: "memory");
}
template <int N>
__device__ __forceinline__ void cp_wait() {
  asm volatile("cp.async.wait_group %0;" :: "n"(N) : "memory");
}
__device__ __forceinline__ void ldsm4(uint32_t* r, uint32_t addr) {
  asm volatile(
      "ldmatrix.sync.aligned.m8n8.x4.shared.b16 {%0,%1,%2,%3}, [%4];"
      : "=r"(r[0]), "=r"(r[1]), "=r"(r[2]), "=r"(r[3]) : "r"(addr));
}
__device__ __forceinline__ void mma_bf16_k16(float* c, const uint32_t* a,
                                             const uint32_t* b) {
  asm volatile(
      "mma.sync.aligned.m16n8k16.row.col.f32.bf16.bf16.f32 "
      "{%0,%1,%2,%3}, {%4,%5,%6,%7}, {%8,%9}, {%0,%1,%2,%3};"
      : "+f"(c[0]), "+f"(c[1]), "+f"(c[2]), "+f"(c[3])
      : "r"(a[0]), "r"(a[1]), "r"(a[2]), "r"(a[3]), "r"(b[0]), "r"(b[1]));
}
__device__ __forceinline__ void mma_f16_k16(float* c, const uint32_t* a,
                                            const uint32_t* b) {
  asm volatile(
      "mma.sync.aligned.m16n8k16.row.col.f32.f16.f16.f32 "
      "{%0,%1,%2,%3}, {%4,%5,%6,%7}, {%8,%9}, {%0,%1,%2,%3};"
      : "+f"(c[0]), "+f"(c[1]), "+f"(c[2]), "+f"(c[3])
      : "r"(a[0]), "r"(a[1]), "r"(a[2]), "r"(a[3]), "r"(b[0]), "r"(b[1]));
}
__device__ __forceinline__ uint32_t pack_bf2(float v) {
  __nv_bfloat16 h = __float2bfloat16_rn(v);
  float fh = __bfloat162float(h);
  __nv_bfloat16 l = __float2bfloat16_rn(v - fh);
  return (uint32_t)__bfloat16_as_ushort(h) |
         ((uint32_t)__bfloat16_as_ushort(l) << 16);
}
__device__ __forceinline__ uint32_t pack_f16p(float a, float b) {
  __half2 h = __floats2half2_rn(a, b);
  return *(uint32_t*)&h;
}

// ---------------------------------------------------------------------------
// GEMM core.  MODE 0 = fast f16-pair; MODE 1 = precise bf16x2 2-MMA.
// op.K, lda, ldb in WORDS. BK = 32 words/chunk, pitch 36 words (144B).
// ---------------------------------------------------------------------------
struct Term { const uint32_t* A; const uint32_t* W; const float* bias; };
struct Op   { Term t[3]; float* C; int nt; int K; int lda; int ldb; int ldc; };
struct OpTable { Op op[9]; };

namespace {
constexpr int GBK = 32;
constexpr int GPITCH = 36;
constexpr int GTILE = 128 * GPITCH;                    // words per buffer
constexpr int GEMM_SMEM = 4 * GTILE * 4;               // 2 bufs x (A+B) = 73728B
}

template <int BN, int MODE, bool PACKOUT>
__device__ __forceinline__ void gemm_core(const Op& op, uint32_t* dsm) {
  constexpr int WN = BN / 2;
  constexpr int NT = WN / 8;
  uint32_t* As = dsm;                  // [2][128*GPITCH]
  uint32_t* Bs = dsm + 2 * GTILE;      // [2][BN*GPITCH]

  const int t = threadIdx.x;
  const int wid = t >> 5, lane = t & 31;
  const int warp_m = wid & 3;
  const int wn = wid >> 2;
  const int gid = lane >> 2, qid = lane & 3;

  const int bm = blockIdx.y * 128;
  const int bn = blockIdx.x * BN;
  const int cpt = op.K / GBK;
  const int total = op.nt * cpt;

  const uint32_t asb = smem_u32(As);
  const uint32_t bsb = smem_u32(Bs);
  const uint32_t a_off =
      (((lane & 15) * GPITCH) + ((lane >> 4) << 2)) * 4;
  const uint32_t b_off =
      ((((lane & 7) + ((lane >> 4) << 3)) * GPITCH) + (((lane >> 3) & 1) << 2)) * 4;

  float acc[2][NT][4];
#pragma unroll
  for (int mt = 0; mt < 2; mt++)
#pragma unroll
    for (int nt = 0; nt < NT; nt++)
#pragma unroll
      for (int j = 0; j < 4; j++) acc[mt][nt][j] = 0.f;

  auto load_chunk = [&](int c, int buf) {
    const int term = c / cpt;
    const int k0 = (c - term * cpt) * GBK;
    const uint32_t* __restrict__ A = op.t[term].A;
    const uint32_t* __restrict__ W = op.t[term].W;
#pragma unroll
    for (int i = 0; i < 4; i++) {        // A: 128 rows x 32 words
      int f = t + i * 256;
      int r = f >> 3, c4 = (f & 7) * 4;
      cp16(&As[buf * GTILE + r * GPITCH + c4],
           A + (size_t)(bm + r) * op.lda + k0 + c4);
    }
#pragma unroll
    for (int i = 0; i < BN / 32; i++) {  // B: BN rows x 32 words
      int f = t + i * 256;
      int r = f >> 3, c4 = (f & 7) * 4;
      cp16(&Bs[buf * GTILE + r * GPITCH + c4],
           W + (size_t)(bn + r) * op.ldb + k0 + c4);
    }
  };

  load_chunk(0, 0);
  cp_commit();

  for (int c = 0; c < total; c++) {
    const int buf = c & 1;
    if (c + 1 < total) load_chunk(c + 1, (c + 1) & 1);
    cp_commit();
    cp_wait<1>();
    __syncthreads();

#pragma unroll
    for (int kk = 0; kk < GBK; kk += 8) {
      uint32_t af[2][4];
#pragma unroll
      for (int mt = 0; mt < 2; mt++) {
        uint32_t ad = asb + a_off +
            (uint32_t)((buf * GTILE + (warp_m * 32 + mt * 16) * GPITCH + kk) * 4);
        ldsm4(af[mt], ad);
      }
#pragma unroll
      for (int nt2 = 0; nt2 < NT / 2; nt2++) {
        uint32_t bf[4];
        uint32_t bd = bsb + b_off +
            (uint32_t)((buf * GTILE + (wn * WN + nt2 * 16) * GPITCH + kk) * 4);
        ldsm4(bf, bd);
#pragma unroll
        for (int half = 0; half < 2; half++) {
          const int nt = nt2 * 2 + half;
          uint32_t u0 = bf[half * 2], u1 = bf[half * 2 + 1];
          if (MODE == 1) {
            uint32_t bh[2] = {__byte_perm(u0, 0, 0x1010),
                              __byte_perm(u1, 0, 0x1010)};
            uint32_t bl[2] = {__byte_perm(u0, 0, 0x3232),
                              __byte_perm(u1, 0, 0x3232)};
#pragma unroll
            for (int mt = 0; mt < 2; mt++) {
              mma_bf16_k16(acc[mt][nt], af[mt], bh);
              mma_bf16_k16(acc[mt][nt], af[mt], bl);
            }
          } else {
            uint32_t br[2] = {u0, u1};
#pragma unroll
            for (int mt = 0; mt < 2; mt++) mma_f16_k16(acc[mt][nt], af[mt], br);
          }
        }
      }
    }
    __syncthreads();
  }

#pragma unroll
  for (int mt = 0; mt < 2; mt++) {
    int row0 = bm + warp_m * 32 + mt * 16 + gid;
#pragma unroll
    for (int nt = 0; nt < NT; nt++) {
      int col = bn + wn * WN + nt * 8 + qid * 2;
      float b0 = 0.f, b1 = 0.f;
      if (op.t[0].bias) {
        for (int tt = 0; tt < op.nt; tt++) {
          b0 += op.t[tt].bias[col];
          b1 += op.t[tt].bias[col + 1];
        }
      }
      float v00 = acc[mt][nt][0] + b0, v01 = acc[mt][nt][1] + b1;
      float v10 = acc[mt][nt][2] + b0, v11 = acc[mt][nt][3] + b1;
      if (PACKOUT) {
        uint32_t* Cp = (uint32_t*)op.C;
        uint2 p0 = {pack_bf2(v00), pack_bf2(v01)};
        uint2 p1 = {pack_bf2(v10), pack_bf2(v11)};
        *(uint2*)(Cp + (size_t)row0 * op.ldc + col) = p0;
        *(uint2*)(Cp + (size_t)(row0 + 8) * op.ldc + col) = p1;
      } else {
        *(float2*)(op.C + (size_t)row0 * op.ldc + col) = {v00, v01};
        *(float2*)(op.C + (size_t)(row0 + 8) * op.ldc + col) = {v10, v11};
      }
    }
  }
}

__global__ void __launch_bounds__(256) proj_precise(const OpTable tab) {
  extern __shared__ uint32_t ds[];
  gemm_core<128, 1, true>(tab.op[blockIdx.z], ds);
}
__global__ void __launch_bounds__(256) proj_f16(const OpTable tab) {
  extern __shared__ uint32_t ds[];
  gemm_core<128, 0, false>(tab.op[blockIdx.z], ds);
}

// ---------------------------------------------------------------------------
// Fused attention (unchanged from R7).
// ---------------------------------------------------------------------------
namespace {
constexpr int TP = 68;
constexpr int QK_W = 128 * TP;
constexpr int VT_W = 64 * TP;
constexpr int FUSED_SMEM = (3 * QK_W + 2 * VT_W + QK_W) * 4;  // 174080 B
}

__global__ void __launch_bounds__(256) fused_attn(
    const uint32_t* __restrict__ qb, const uint32_t* __restrict__ kb,
    const uint32_t* __restrict__ vtb, const float* __restrict__ bias0,
    const float* __restrict__ bias1, const float* __restrict__ bias2,
    float* __restrict__ score_out, uint32_t* __restrict__ ofb) {
  extern __shared__ uint32_t sm[];
  uint32_t* Qs = sm;
  uint32_t* Ks = sm + QK_W;
  uint32_t* VT = sm + 3 * QK_W;
  uint32_t* Ps = sm + 3 * QK_W + 2 * VT_W;

  const int zz = blockIdx.y;
  const int st = zz >> 5, bh = zz & 31, b = bh >> 4, h = bh & 15;
  const int q0 = blockIdx.x * 128;

  const uint32_t* qp = qb + (size_t)st * NTOK + (size_t)(b * S_ + q0) * DH_ + h * HD_;
  const uint32_t* kp = kb + (size_t)st * NTOK + (size_t)b * S_ * DH_ + h * HD_;
  const uint32_t* vtp = vtb + (size_t)zz * (HD_ * S_ / 2);
  const float* bias = (st == 0) ? bias0 : (st == 1) ? bias1 : bias2;
  const float* brow = bias + (size_t)bh * S_ * S_ + (size_t)q0 * S_;
  float* srow = score_out + (size_t)st * NSC + (size_t)bh * S_ * S_ + (size_t)q0 * S_;
  uint32_t* ofp = ofb + (size_t)st * (NTOK / 2) + (size_t)(b * S_ + q0) * (DH_ / 2) + h * (HD_ / 2);

  const int t = threadIdx.x;
  const int w = t >> 5, lane = t & 31;
  const int gid = lane >> 2, qid = lane & 3;
  const int r0 = w * 16 + gid;

  const uint32_t smb = smem_u32(sm);
  const uint32_t a_off =
      (((lane & 15) * TP) + ((lane >> 4) << 2)) * 4;
  const uint32_t b_off =
      ((((lane & 7) + ((lane >> 4) << 3)) * TP) + (((lane >> 3) & 1) << 2)) * 4;

  auto load_q = [&]() {
#pragma unroll
    for (int i = 0; i < 8; i++) {
      int f = t + i * 256;
      int r = f >> 4, c4 = (f & 15) * 4;
      cp16(&Qs[r * TP + c4], qp + (size_t)r * DH_ + c4);
    }
  };
  auto load_kv = [&](int kbk, int buf) {
#pragma unroll
    for (int i = 0; i < 8; i++) {
      int f = t + i * 256;
      int r = f >> 4, c4 = (f & 15) * 4;
      cp16(&Ks[buf * QK_W + r * TP + c4],
           kp + (size_t)(kbk * 128 + r) * DH_ + c4);
    }
#pragma unroll
    for (int i = 0; i < 4; i++) {
      int f = t + i * 256;
      int r = f >> 4, c4 = (f & 15) * 4;
      cp16(&VT[buf * VT_W + r * TP + c4],
           vtp + (size_t)r * (S_ / 2) + kbk * 64 + c4);
    }
  };

  load_q();
  load_kv(0, 0);
  cp_commit();
  load_kv(1, 1);
  cp_commit();

  float m0 = -1e30f, m1 = -1e30f, l0 = 0.f, l1 = 0.f;
  float oacc[8][4];
#pragma unroll
  for (int j = 0; j < 8; j++)
#pragma unroll
    for (int q = 0; q < 4; q++) oacc[j][q] = 0.f;

  const uint32_t q_base = smb + a_off + (uint32_t)(w * 16 * TP * 4);
  const uint32_t p_base = smb + a_off +
      (uint32_t)((3 * QK_W + 2 * VT_W + w * 16 * TP) * 4);

  for (int it = 0; it < 8; it++) {
    const int buf = it & 1;
    cp_wait<1>();
    __syncthreads();

    float acc[16][4];
#pragma unroll
    for (int nt = 0; nt < 16; nt++)
#pragma unroll
      for (int q = 0; q < 4; q++) acc[nt][q] = 0.f;

#pragma unroll
    for (int kk = 0; kk < 64; kk += 8) {
      uint32_t af[4];
      ldsm4(af, q_base + (uint32_t)(kk * 4));
#pragma unroll
      for (int nt2 = 0; nt2 < 8; nt2++) {
        uint32_t kf[4];
        uint32_t kd = smb + b_off +
            (uint32_t)((QK_W + buf * QK_W + nt2 * 16 * TP + kk) * 4);
        ldsm4(kf, kd);
#pragma unroll
        for (int half = 0; half < 2; half++) {
          const int nt = nt2 * 2 + half;
          uint32_t u0 = kf[half * 2], u1 = kf[half * 2 + 1];
          uint32_t bh2[2] = {__byte_perm(u0, 0, 0x1010), __byte_perm(u1, 0, 0x1010)};
          uint32_t bl2[2] = {__byte_perm(u0, 0, 0x3232), __byte_perm(u1, 0, 0x3232)};
          mma_bf16_k16(acc[nt], af, bh2);
          mma_bf16_k16(acc[nt], af, bl2);
        }
      }
    }

    const int cbase = it * 128;
#pragma unroll
    for (int nt = 0; nt < 16; nt++) {
      int col = cbase + nt * 8 + qid * 2;
      *(float2*)(srow + (size_t)(r0)     * S_ + col) = {acc[nt][0], acc[nt][1]};
      *(float2*)(srow + (size_t)(r0 + 8) * S_ + col) = {acc[nt][2], acc[nt][3]};
      float2 bv0 = *(const float2*)(brow + (size_t)(r0)     * S_ + col);
      float2 bv1 = *(const float2*)(brow + (size_t)(r0 + 8) * S_ + col);
      acc[nt][0] += bv0.x; acc[nt][1] += bv0.y;
      acc[nt][2] += bv1.x; acc[nt][3] += bv1.y;
    }

    float mt0 = -1e30f, mt1 = -1e30f;
#pragma unroll
    for (int nt = 0; nt < 16; nt++) {
      mt0 = fmaxf(mt0, fmaxf(acc[nt][0], acc[nt][1]));
      mt1 = fmaxf(mt1, fmaxf(acc[nt][2], acc[nt][3]));
    }
    mt0 = fmaxf(mt0, __shfl_xor_sync(0xffffffffu, mt0, 1));
    mt0 = fmaxf(mt0, __shfl_xor_sync(0xffffffffu, mt0, 2));
    mt1 = fmaxf(mt1, __shfl_xor_sync(0xffffffffu, mt1, 1));
    mt1 = fmaxf(mt1, __shfl_xor_sync(0xffffffffu, mt1, 2));

    float m0n = fmaxf(m0, mt0), m1n = fmaxf(m1, mt1);
    float sc0 = __expf(m0 - m0n), sc1 = __expf(m1 - m1n);
    m0 = m0n; m1 = m1n;
    l0 *= sc0; l1 *= sc1;
#pragma unroll
    for (int j = 0; j < 8; j++) {
      oacc[j][0] *= sc0; oacc[j][1] *= sc0;
      oacc[j][2] *= sc1; oacc[j][3] *= sc1;
    }

    float ts0 = 0.f, ts1 = 0.f;
#pragma unroll
    for (int nt = 0; nt < 16; nt++) {
      float p00 = __expf(acc[nt][0] - m0);
      float p01 = __expf(acc[nt][1] - m0);
      float p10 = __expf(acc[nt][2] - m1);
      float p11 = __expf(acc[nt][3] - m1);
      ts0 += p00 + p01; ts1 += p10 + p11;
      Ps[(r0)     * TP + nt * 4 + qid] = pack_f16p(p00, p01);
      Ps[(r0 + 8) * TP + nt * 4 + qid] = pack_f16p(p10, p11);
    }
    ts0 += __shfl_xor_sync(0xffffffffu, ts0, 1);
    ts0 += __shfl_xor_sync(0xffffffffu, ts0, 2);
    ts1 += __shfl_xor_sync(0xffffffffu, ts1, 1);
    ts1 += __shfl_xor_sync(0xffffffffu, ts1, 2);
    l0 += ts0; l1 += ts1;
    __syncwarp();

#pragma unroll
    for (int kw = 0; kw < 64; kw += 8) {
      uint32_t ap[4];
      ldsm4(ap, p_base + (uint32_t)(kw * 4));
#pragma unroll
      for (int j2 = 0; j2 < 4; j2++) {
        uint32_t vf[4];
        uint32_t vd = smb + b_off +
            (uint32_t)((3 * QK_W + buf * VT_W + j2 * 16 * TP + kw) * 4);
        ldsm4(vf, vd);
        mma_f16_k16(oacc[j2 * 2],     ap, vf);
        mma_f16_k16(oacc[j2 * 2 + 1], ap, vf + 2);
      }
    }
    __syncthreads();

    if (it + 2 < 8) load_kv(it + 2, buf);
    cp_commit();
  }

  float inv0 = 1.f / l0, inv1 = 1.f / l1;
#pragma unroll
  for (int j = 0; j < 8; j++) {
    int cw = j * 4 + qid;
    ofp[(size_t)(r0)     * (DH_ / 2) + cw] =
        pack_f16p(oacc[j][0] * inv0, oacc[j][1] * inv0);
    ofp[(size_t)(r0 + 8) * (DH_ / 2) + cw] =
        pack_f16p(oacc[j][2] * inv1, oacc[j][3] * inv1);
  }
}

// ---- fused input packing ----
__global__ void __launch_bounds__(256) pack_all(
    const float* __restrict__ y, const float* __restrict__ s,
    const float* __restrict__ b, const float* __restrict__ z,
    uint32_t* __restrict__ ypk, uint32_t* __restrict__ spk,
    uint32_t* __restrict__ bpk, uint32_t* __restrict__ zpk,
    uint32_t* __restrict__ sfh, uint32_t* __restrict__ bfh,
    uint32_t* __restrict__ zfh) {
  const int which = blockIdx.y;
  const int i2 = blockIdx.x * 256 + threadIdx.x;
  const float* src; uint32_t* d_bf; uint32_t* d_fh; int npair;
  switch (which) {
    case 0: src = y; d_bf = ypk; d_fh = nullptr; npair = M_ * DIN_ / 2; break;
    case 1: src = s; d_bf = spk; d_fh = sfh; npair = M_ * DH_ / 2; break;
    case 2: src = b; d_bf = bpk; d_fh = bfh; npair = M_ * DH_ / 2; break;
    default: src = z; d_bf = zpk; d_fh = zfh; npair = M_ * DH_ / 2; break;
  }
  if (i2 >= npair) return;
  float2 v = *(const float2*)(src + 2 * i2);
  d_bf[2 * i2]     = pack_bf2(v.x);
  d_bf[2 * i2 + 1] = pack_bf2(v.y);
  if (d_fh) d_fh[i2] = pack_f16p(v.x, v.y);
}

// ---- weight transpose ----
struct WEnt { const float* src; uint32_t* dst; int K; int pack; };
struct WTab { WEnt e[12]; };

__global__ void __launch_bounds__(256) transpose_w(const WTab tab) {
  WEnt e = tab.e[blockIdx.z];
  int n0 = blockIdx.x * 32, k0 = blockIdx.y * 32;
  if (k0 >= e.K) return;
  __shared__ float tl[32][33];
  int tx = threadIdx.x, ty = threadIdx.y;
#pragma unroll
  for (int i = 0; i < 32; i += 8)
    tl[ty + i][tx] = e.src[(size_t)(k0 + ty + i) * DH_ + n0 + tx];
  __syncthreads();
  if (e.pack == 1) {
#pragma unroll
    for (int i = 0; i < 32; i += 8)
      e.dst[(size_t)(n0 + ty + i) * e.K + k0 + tx] = pack_bf2(tl[tx][ty + i]);
  } else {
    if (tx < 16) {
#pragma unroll
      for (int i = 0; i < 32; i += 8) {
        int nn = ty + i;
        e.dst[(size_t)(n0 + nn) * (e.K / 2) + k0 / 2 + tx] =
            pack_f16p(tl[2 * tx][nn], tl[2 * tx + 1][nn]);
      }
    }
  }
}

// ---- V transpose ----
__global__ void __launch_bounds__(256) transpose_v(const float* __restrict__ v,
                                                   uint32_t* __restrict__ vt) {
  int z = blockIdx.z, st = z >> 5, bh = z & 31, b = bh >> 4, h = bh & 15;
  int c0 = blockIdx.x * 32, k0 = blockIdx.y * 32;
  __shared__ float tl[32][33];
  int tx = threadIdx.x, ty = threadIdx.y;
  const float* src = v + (size_t)st * NTOK + (size_t)b * S_ * DH_ + h * HD_;
  uint32_t* dst = vt + (size_t)z * (HD_ * S_ / 2);
#pragma unroll
  for (int i = 0; i < 32; i += 8)
    tl[ty + i][tx] = src[(size_t)(k0 + ty + i) * DH_ + c0 + tx];
  __syncthreads();
  if (tx < 16) {
#pragma unroll
    for (int i = 0; i < 32; i += 8) {
      int cc = ty + i;
      dst[(size_t)(c0 + cc) * (S_ / 2) + k0 / 2 + tx] =
          pack_f16p(tl[2 * tx][cc], tl[2 * tx + 1][cc]);
    }
  }
}

// ---- residual chain ----
__global__ void __launch_bounds__(256) combine_kernel(
    const float* __restrict__ s, const float* __restrict__ b,
    const float* __restrict__ z, const float* __restrict__ ps,
    const float* __restrict__ pb, const float* __restrict__ pz,
    float* __restrict__ os, float* __restrict__ ob, float* __restrict__ oz) {
  size_t i = (size_t)blockIdx.x * 256 + threadIdx.x;
  if (i >= NTOK) return;
  float so = s[i] + ps[i];
  float bo = so + b[i] + pb[i];
  float zo = bo + z[i] + pz[i];
  os[i] = so; ob[i] = bo; oz[i] = zo;
}

// ===========================================================================
extern "C" void kernel_launch(void* const* d_in, const int* in_sizes, int n_in,
                              void* d_out, int out_size) {
  const float* y    = (const float*)d_in[0];
  const float* s    = (const float*)d_in[1];
  const float* b    = (const float*)d_in[2];
  const float* z    = (const float*)d_in[3];
  const float* ba0  = (const float*)d_in[4];
  const float* ba1  = (const float*)d_in[5];
  const float* ba2  = (const float*)d_in[6];
  const float* W[12] = {
      (const float*)d_in[7],  (const float*)d_in[9],  (const float*)d_in[11],
      (const float*)d_in[13], (const float*)d_in[15], (const float*)d_in[17],
      (const float*)d_in[19], (const float*)d_in[21],
      (const float*)d_in[23], (const float*)d_in[25], (const float*)d_in[27],
      (const float*)d_in[29]};
  const float* C[12] = {
      (const float*)d_in[8],  (const float*)d_in[10], (const float*)d_in[12],
      (const float*)d_in[14], (const float*)d_in[16], (const float*)d_in[18],
      (const float*)d_in[20], (const float*)d_in[22],
      (const float*)d_in[24], (const float*)d_in[26], (const float*)d_in[28],
      (const float*)d_in[30]};
  const int KW[12] = {DIN_, DIN_, DIN_, DH_, DH_, DH_, DH_, DH_,
                      DH_, DH_, DH_, DH_};

  float* out   = (float*)d_out;
  float* s_out = out;
  float* b_out = out + NTOK;
  float* z_out = out + 2 * NTOK;
  float* scb   = out + 3 * NTOK;

  uint32_t *gq, *gk, *gof, *gwtf, *gvth, *gyp, *gsp, *gbp, *gzp, *gsf, *gbf, *gzf;
  float *gv, *gp, *gwt;
  cudaGetSymbolAddress((void**)&gq, g_q);
  cudaGetSymbolAddress((void**)&gk, g_k);
  cudaGetSymbolAddress((void**)&gv, g_v);
  cudaGetSymbolAddress((void**)&gof, g_of);
  cudaGetSymbolAddress((void**)&gp, g_p);
  cudaGetSymbolAddress((void**)&gwt, g_wt);
  cudaGetSymbolAddress((void**)&gwtf, g_wtf);
  cudaGetSymbolAddress((void**)&gvth, g_vth);
  cudaGetSymbolAddress((void**)&gyp, g_ypk);
  cudaGetSymbolAddress((void**)&gsp, g_spk);
  cudaGetSymbolAddress((void**)&gbp, g_bpk);
  cudaGetSymbolAddress((void**)&gzp, g_zpk);
  cudaGetSymbolAddress((void**)&gsf, g_sfh);
  cudaGetSymbolAddress((void**)&gbf, g_bfh);
  cudaGetSymbolAddress((void**)&gzf, g_zfh);

  cudaFuncSetAttribute(fused_attn, cudaFuncAttributeMaxDynamicSharedMemorySize,
                       FUSED_SMEM);
  cudaFuncSetAttribute(proj_precise, cudaFuncAttributeMaxDynamicSharedMemorySize,
                       GEMM_SMEM);
  cudaFuncSetAttribute(proj_f16, cudaFuncAttributeMaxDynamicSharedMemorySize,
                       GEMM_SMEM);

  // --- 1a: pack all inputs ---
  pack_all<<<dim3(4096, 4), 256>>>(y, s, b, z, gyp, gsp, gbp, gzp,
                                   gsf, gbf, gzf);

  // --- 1b: transpose weights ---
  WTab wt{};
  for (int i = 0; i < 8; i++)
    wt.e[i] = {W[i], (uint32_t*)(gwt + (size_t)i * DH_ * DH_), KW[i], 1};
  for (int i = 8; i < 12; i++)
    wt.e[i] = {W[i], gwtf + (size_t)(i - 8) * (DH_ * DH_ / 2), KW[i], 2};
  transpose_w<<<dim3(32, 32, 12), dim3(32, 8)>>>(wt);

  auto WTp = [&](int i) -> const uint32_t* {
    return (const uint32_t*)(gwt + (size_t)i * DH_ * DH_);
  };
  auto WTf = [&](int i) -> const uint32_t* {
    return gwtf + (size_t)(i - 8) * (DH_ * DH_ / 2);
  };

  // --- 2a: Q + K projections (precise) ---
  OpTable tqk{};
  auto setp = [&](int idx, uint32_t* Cp, int K, int nt,
                  const uint32_t* A0, int w0,
                  const uint32_t* A1 = nullptr, int w1 = -1,
                  const uint32_t* A2 = nullptr, int w2 = -1) {
    Op& o = tqk.op[idx];
    o.C = (float*)Cp; o.K = K; o.nt = nt; o.lda = K; o.ldb = K; o.ldc = DH_;
    o.t[0] = {A0, WTp(w0), C[w0]};
    if (nt > 1) o.t[1] = {A1, WTp(w1), C[w1]};
    if (nt > 2) o.t[2] = {A2, WTp(w2), C[w2]};
  };
  setp(0, gq + 0 * NTOK, DIN_, 1, gyp, 0);
  setp(1, gq + 1 * NTOK, DIN_, 1, gyp, 1);
  setp(2, gq + 2 * NTOK, DIN_, 1, gyp, 2);
  setp(3, gk + 0 * NTOK, DH_, 2, gsp, 3, gbp, 4);
  setp(4, gk + 1 * NTOK, DH_, 3, gbp, 6, gsp, 4, gzp, 5);
  setp(5, gk + 2 * NTOK, DH_, 2, gzp, 7, gbp, 5);
  proj_precise<<<dim3(8, 16, 6), 256, GEMM_SMEM>>>(tqk);

  // --- 2b: V projections (f16) ---
  OpTable tv{};
  const uint32_t* fin[3] = {gsf, gbf, gzf};
  for (int i = 0; i < 3; i++) {
    Op& o = tv.op[i];
    o.C = gv + (size_t)i * NTOK; o.K = DH_ / 2; o.nt = 1;
    o.lda = DH_ / 2; o.ldb = DH_ / 2; o.ldc = DH_;
    o.t[0] = {fin[i], WTf(8 + i), C[8 + i]};
  }
  proj_f16<<<dim3(8, 16, 3), 256, GEMM_SMEM>>>(tv);

  // --- 3: V transpose ---
  transpose_v<<<dim3(2, 32, 96), dim3(32, 8)>>>(gv, gvth);

  // --- 4: fused attention ---
  fused_attn<<<dim3(8, 96), 256, FUSED_SMEM>>>(gq, gk, gvth, ba0, ba1, ba2,
                                               scb, gof);

  // --- 5: output projections (f16) ---
  OpTable to{};
  for (int i = 0; i < 3; i++) {
    Op& o = to.op[i];
    o.C = gp + (size_t)i * NTOK; o.K = DH_ / 2; o.nt = 1;
    o.lda = DH_ / 2; o.ldb = DH_ / 2; o.ldc = DH_;
    o.t[0] = {gof + (size_t)i * (NTOK / 2), WTf(11), C[11]};
  }
  proj_f16<<<dim3(8, 16, 3), 256, GEMM_SMEM>>>(to);

  // --- 6: residual chain ---
  combine_kernel<<<(int)((NTOK + 255) / 256), 256>>>(
      s, b, z, gp + 0 * NTOK, gp + 1 * NTOK, gp + 2 * NTOK,
      s_out, b_out, z_out);
}